// round 1
// baseline (speedup 1.0000x reference)
#include <cuda_runtime.h>
#include <math.h>

#define B_  16
#define N_  4096
#define M_  1024
#define C_  256
#define KIN 512

// Scratch (static device globals; allocation is forbidden in kernel_launch)
__device__ float g_interp[(size_t)B_ * C_ * N_];   // [B,256,N] interpolated feat2
__device__ float g_h1[(size_t)B_ * C_ * N_];       // [B,256,N] hidden activations
__device__ int   g_idx[B_ * N_ * 3];
__device__ float g_w[B_ * N_ * 3];

// ---------------------------------------------------------------------------
// Kernel 1: 3-NN over M=1024 candidates per query point.
// One thread per query; candidates staged through smem as float4 (x,y,z,|p|^2)
// so the inner loop is 1 broadcast LDS.128 + 4 FMA + compare chain.
// d2 computed as (s1 + s2) - 2*dot to match the reference formula exactly.
// Strict '<' keeps the earliest index on ties (lax.top_k tie-break).
// ---------------------------------------------------------------------------
__global__ void knn_kernel(const float* __restrict__ xyz1,
                           const float* __restrict__ xyz2)
{
    __shared__ float4 sp[256];
    const int tid = threadIdx.x;
    const int b   = blockIdx.y;
    const int n   = blockIdx.x * 256 + tid;

    const float* p1 = xyz1 + ((size_t)b * N_ + n) * 3;
    const float px = p1[0], py = p1[1], pz = p1[2];
    const float s1 = px * px + py * py + pz * pz;

    float b0 = 3.4e38f, b1 = 3.4e38f, b2 = 3.4e38f;
    int   i0 = 0, i1 = 0, i2 = 0;

    for (int mt = 0; mt < M_; mt += 256) {
        const float* p2 = xyz2 + ((size_t)b * M_ + mt + tid) * 3;
        float x = p2[0], y = p2[1], z = p2[2];
        __syncthreads();
        sp[tid] = make_float4(x, y, z, x * x + y * y + z * z);
        __syncthreads();
        #pragma unroll 8
        for (int j = 0; j < 256; ++j) {
            float4 q = sp[j];
            float dot = px * q.x + py * q.y + pz * q.z;
            float d2  = (s1 + q.w) - 2.0f * dot;
            int   m   = mt + j;
            if (d2 < b2) {
                if (d2 < b1) {
                    if (d2 < b0) { b2 = b1; i2 = i1; b1 = b0; i1 = i0; b0 = d2; i0 = m; }
                    else         { b2 = b1; i2 = i1; b1 = d2; i1 = m; }
                } else           { b2 = d2; i2 = m; }
            }
        }
    }

    float w0 = 1.0f / (b0 + 1e-8f);
    float w1 = 1.0f / (b1 + 1e-8f);
    float w2 = 1.0f / (b2 + 1e-8f);
    float ws = w0 + w1 + w2;

    size_t base = ((size_t)b * N_ + n) * 3;
    g_idx[base + 0] = i0; g_idx[base + 1] = i1; g_idx[base + 2] = i2;
    g_w[base + 0] = w0 / ws; g_w[base + 1] = w1 / ws; g_w[base + 2] = w2 / ws;
}

// ---------------------------------------------------------------------------
// Kernel 2: weighted 3-point gather of feat2 -> g_interp [B,256,N].
// Each thread keeps its (idx,w) triple in registers and produces 4 channels,
// amortizing the idx/w traffic 4x. feat2 (16 MB) is fully L2-resident.
// ---------------------------------------------------------------------------
__global__ void interp_kernel(const float* __restrict__ feat2)
{
    const int tid = threadIdx.x;
    const int n   = blockIdx.x * 256 + tid;
    const int c0  = blockIdx.y;          // 0..63
    const int b   = blockIdx.z;

    size_t base = ((size_t)b * N_ + n) * 3;
    int   i0 = g_idx[base + 0], i1 = g_idx[base + 1], i2 = g_idx[base + 2];
    float w0 = g_w[base + 0],   w1 = g_w[base + 1],   w2 = g_w[base + 2];

    #pragma unroll
    for (int j = 0; j < 4; ++j) {
        int c = c0 + j * 64;
        const float* f = feat2 + ((size_t)b * C_ + c) * M_;
        g_interp[((size_t)b * C_ + c) * N_ + n] =
            w0 * f[i0] + w1 * f[i1] + w2 * f[i2];
    }
}

// ---------------------------------------------------------------------------
// Kernel 3/4: batched SGEMM  Y[b] = relu( (W @ X[b]) * (gamma/sqrt(1+eps)) + beta )
// W:[O,K] row-major, X[b]:[K,N_] row-major split across two sources at Ksplit
// (GEMM1: rows <256 from g_interp, rows >=256 from feat1 -> avoids a concat copy).
// 128x128 tile, BK=16, 8x8 micro-tile per thread, 256 threads, 2 CTAs/SM.
// ---------------------------------------------------------------------------
__global__ __launch_bounds__(256, 2)
void sgemm_bn_relu(const float* __restrict__ W,
                   const float* __restrict__ X0,
                   const float* __restrict__ X1,
                   float*       __restrict__ Y,
                   const float* __restrict__ gamma,
                   const float* __restrict__ beta,
                   int K, int Ksplit, size_t xbstride, size_t ybstride)
{
    const int BM = 128, BN = 128, BK = 16;
    __shared__ float As[BK][BM + 4];   // +4 pad: avoid transpose-store conflicts
    __shared__ float Bs[BK][BN];

    const int tid = threadIdx.x;
    const int bn  = blockIdx.x * BN;
    const int bo  = blockIdx.y * BM;
    const int b   = blockIdx.z;

    const float* x0 = X0 + (size_t)b * xbstride;
    const float* x1 = X1 + (size_t)b * xbstride;

    float acc[8][8];
    #pragma unroll
    for (int i = 0; i < 8; ++i)
        #pragma unroll
        for (int j = 0; j < 8; ++j) acc[i][j] = 0.0f;

    const int aRow = tid >> 2;          // 0..63
    const int aK4  = (tid & 3) * 4;     // 0,4,8,12
    const int bRow = tid >> 5;          // 0..7
    const int bCol = (tid & 31) * 4;    // 0..124
    const int ty   = tid >> 4;          // 0..15 (o micro-tile)
    const int tx   = tid & 15;          // 0..15 (n micro-tile)

    for (int kt = 0; kt < K; kt += BK) {
        // A tile: W[bo..bo+127][kt..kt+15], stored transposed As[k][o]
        #pragma unroll
        for (int r = 0; r < 2; ++r) {
            int o = bo + aRow + r * 64;
            float4 v = *(const float4*)(W + (size_t)o * K + kt + aK4);
            As[aK4 + 0][aRow + r * 64] = v.x;
            As[aK4 + 1][aRow + r * 64] = v.y;
            As[aK4 + 2][aRow + r * 64] = v.z;
            As[aK4 + 3][aRow + r * 64] = v.w;
        }
        // B tile: X[kt..kt+15][bn..bn+127]  (row source switches at Ksplit)
        #pragma unroll
        for (int r = 0; r < 2; ++r) {
            int kl = bRow + r * 8;
            int kg = kt + kl;
            const float* src = (kg < Ksplit)
                             ? (x0 + (size_t)kg * N_)
                             : (x1 + (size_t)(kg - Ksplit) * N_);
            *(float4*)&Bs[kl][bCol] = *(const float4*)(src + bn + bCol);
        }
        __syncthreads();

        #pragma unroll
        for (int kk = 0; kk < BK; ++kk) {
            float a[8], bb[8];
            #pragma unroll
            for (int i = 0; i < 8; ++i) a[i]  = As[kk][ty * 8 + i];
            #pragma unroll
            for (int j = 0; j < 8; ++j) bb[j] = Bs[kk][tx * 8 + j];
            #pragma unroll
            for (int i = 0; i < 8; ++i)
                #pragma unroll
                for (int j = 0; j < 8; ++j)
                    acc[i][j] = fmaf(a[i], bb[j], acc[i][j]);
        }
        __syncthreads();
    }

    const float bninv = 0.9999950000374997f;  // 1/sqrt(1 + 1e-5)
    float* y = Y + (size_t)b * ybstride;
    #pragma unroll
    for (int i = 0; i < 8; ++i) {
        int o = bo + ty * 8 + i;
        float g  = gamma[o] * bninv;
        float bt = beta[o];
        float* yr = y + (size_t)o * N_ + bn + tx * 8;
        float4 v0, v1;
        v0.x = fmaxf(fmaf(acc[i][0], g, bt), 0.0f);
        v0.y = fmaxf(fmaf(acc[i][1], g, bt), 0.0f);
        v0.z = fmaxf(fmaf(acc[i][2], g, bt), 0.0f);
        v0.w = fmaxf(fmaf(acc[i][3], g, bt), 0.0f);
        v1.x = fmaxf(fmaf(acc[i][4], g, bt), 0.0f);
        v1.y = fmaxf(fmaf(acc[i][5], g, bt), 0.0f);
        v1.z = fmaxf(fmaf(acc[i][6], g, bt), 0.0f);
        v1.w = fmaxf(fmaf(acc[i][7], g, bt), 0.0f);
        *(float4*)(yr + 0) = v0;
        *(float4*)(yr + 4) = v1;
    }
}

// ---------------------------------------------------------------------------
extern "C" void kernel_launch(void* const* d_in, const int* in_sizes, int n_in,
                              void* d_out, int out_size)
{
    const float* xyz1   = (const float*)d_in[0];
    const float* xyz2   = (const float*)d_in[1];
    const float* feat1  = (const float*)d_in[2];
    const float* feat2  = (const float*)d_in[3];
    const float* w1     = (const float*)d_in[4];
    const float* gamma1 = (const float*)d_in[5];
    const float* beta1  = (const float*)d_in[6];
    const float* w2     = (const float*)d_in[7];
    const float* gamma2 = (const float*)d_in[8];
    const float* beta2  = (const float*)d_in[9];
    float* out = (float*)d_out;

    float *interp, *h1;
    cudaGetSymbolAddress((void**)&interp, g_interp);
    cudaGetSymbolAddress((void**)&h1,     g_h1);

    dim3 gknn(N_ / 256, B_);
    knn_kernel<<<gknn, 256>>>(xyz1, xyz2);

    dim3 gint(N_ / 256, 64, B_);
    interp_kernel<<<gint, 256>>>(feat2);

    dim3 gg(N_ / 128, C_ / 128, B_);
    // GEMM1: K=512, rows [0,256) from interp, rows [256,512) from feat1
    sgemm_bn_relu<<<gg, 256>>>(w1, interp, feat1, h1, gamma1, beta1,
                               KIN, C_, (size_t)C_ * N_, (size_t)C_ * N_);
    // GEMM2: K=256, all rows from h1
    sgemm_bn_relu<<<gg, 256>>>(w2, h1, h1, out, gamma2, beta2,
                               C_, C_, (size_t)C_ * N_, (size_t)C_ * N_);
}

// round 4
// speedup vs baseline: 2.1567x; 2.1567x over previous
#include <cuda_runtime.h>
#include <cuda_bf16.h>
#include <cstdint>
#include <cstddef>

#define B_  16
#define N_  4096
#define M_  1024
#define C_  256
#define KIN 512

typedef __nv_bfloat16 bf16;

// ---------------------------------------------------------------------------
// Scratch (static device globals; allocation is forbidden in kernel_launch)
// ---------------------------------------------------------------------------
__device__ __align__(16) bf16 g_interp_hi[(size_t)B_ * C_ * N_];
__device__ __align__(16) bf16 g_interp_lo[(size_t)B_ * C_ * N_];
__device__ __align__(16) bf16 g_feat1_hi[(size_t)B_ * C_ * N_];
__device__ __align__(16) bf16 g_feat1_lo[(size_t)B_ * C_ * N_];
__device__ __align__(16) bf16 g_h1_hi[(size_t)B_ * C_ * N_];
__device__ __align__(16) bf16 g_h1_lo[(size_t)B_ * C_ * N_];
__device__ __align__(16) bf16 g_w1_hi[C_ * KIN], g_w1_lo[C_ * KIN];
__device__ __align__(16) bf16 g_w2_hi[C_ * C_],  g_w2_lo[C_ * C_];
__device__ int   g_idx[B_ * N_ * 3];
__device__ float g_wt[B_ * N_ * 3];

// ---------------------------------------------------------------------------
// PTX helpers (all architecture-portable: sm_80+ instructions only)
// ---------------------------------------------------------------------------
static __device__ __forceinline__ uint32_t smem_u32(const void* p) {
    uint32_t a;
    asm("{ .reg .u64 t; cvta.to.shared.u64 t, %1; cvt.u32.u64 %0, t; }"
        : "=r"(a) : "l"(p));
    return a;
}
static __device__ __forceinline__ void cp16(uint32_t s, const void* g) {
    asm volatile("cp.async.cg.shared.global [%0], [%1], 16;" :: "r"(s), "l"(g));
}
static __device__ __forceinline__ void ldsm4(uint32_t* r, uint32_t a) {
    asm volatile("ldmatrix.sync.aligned.m8n8.x4.shared.b16 {%0,%1,%2,%3}, [%4];"
                 : "=r"(r[0]), "=r"(r[1]), "=r"(r[2]), "=r"(r[3]) : "r"(a));
}
static __device__ __forceinline__ void ldsm4t(uint32_t* r, uint32_t a) {
    asm volatile("ldmatrix.sync.aligned.m8n8.x4.trans.shared.b16 {%0,%1,%2,%3}, [%4];"
                 : "=r"(r[0]), "=r"(r[1]), "=r"(r[2]), "=r"(r[3]) : "r"(a));
}
static __device__ __forceinline__ void mma_bf16(float* c, const uint32_t* a,
                                                const uint32_t* b) {
    asm volatile(
        "mma.sync.aligned.m16n8k16.row.col.f32.bf16.bf16.f32 "
        "{%0,%1,%2,%3}, {%4,%5,%6,%7}, {%8,%9}, {%0,%1,%2,%3};"
        : "+f"(c[0]), "+f"(c[1]), "+f"(c[2]), "+f"(c[3])
        : "r"(a[0]), "r"(a[1]), "r"(a[2]), "r"(a[3]), "r"(b[0]), "r"(b[1]));
}

// ---------------------------------------------------------------------------
// Kernel 1: 3-NN (unchanged from the passing R1 kernel)
// ---------------------------------------------------------------------------
__global__ void knn_kernel(const float* __restrict__ xyz1,
                           const float* __restrict__ xyz2)
{
    __shared__ float4 sp[256];
    const int tid = threadIdx.x;
    const int b   = blockIdx.y;
    const int n   = blockIdx.x * 256 + tid;

    const float* p1 = xyz1 + ((size_t)b * N_ + n) * 3;
    const float px = p1[0], py = p1[1], pz = p1[2];
    const float s1 = px * px + py * py + pz * pz;

    float b0 = 3.4e38f, b1 = 3.4e38f, b2 = 3.4e38f;
    int   i0 = 0, i1 = 0, i2 = 0;

    for (int mt = 0; mt < M_; mt += 256) {
        const float* p2 = xyz2 + ((size_t)b * M_ + mt + tid) * 3;
        float x = p2[0], y = p2[1], z = p2[2];
        __syncthreads();
        sp[tid] = make_float4(x, y, z, x * x + y * y + z * z);
        __syncthreads();
        #pragma unroll 8
        for (int j = 0; j < 256; ++j) {
            float4 q = sp[j];
            float dot = px * q.x + py * q.y + pz * q.z;
            float d2  = (s1 + q.w) - 2.0f * dot;
            int   m   = mt + j;
            if (d2 < b2) {
                if (d2 < b1) {
                    if (d2 < b0) { b2 = b1; i2 = i1; b1 = b0; i1 = i0; b0 = d2; i0 = m; }
                    else         { b2 = b1; i2 = i1; b1 = d2; i1 = m; }
                } else           { b2 = d2; i2 = m; }
            }
        }
    }

    float w0 = 1.0f / (b0 + 1e-8f);
    float w1 = 1.0f / (b1 + 1e-8f);
    float w2 = 1.0f / (b2 + 1e-8f);
    float ws = w0 + w1 + w2;

    size_t base = ((size_t)b * N_ + n) * 3;
    g_idx[base + 0] = i0; g_idx[base + 1] = i1; g_idx[base + 2] = i2;
    g_wt[base + 0] = w0 / ws; g_wt[base + 1] = w1 / ws; g_wt[base + 2] = w2 / ws;
}

// ---------------------------------------------------------------------------
// Kernel 2: weighted 3-point gather -> interp, written pre-split bf16 hi/lo.
// Each thread handles 2 adjacent n (packed u32 stores) x 4 channels.
// ---------------------------------------------------------------------------
__global__ void interp_kernel(const float* __restrict__ feat2)
{
    const int tid = threadIdx.x;
    const int n   = (blockIdx.x * 256 + tid) * 2;
    const int c0  = blockIdx.y;          // 0..63
    const int b   = blockIdx.z;

    size_t ba = ((size_t)b * N_ + n) * 3;
    int   i0 = g_idx[ba+0], i1 = g_idx[ba+1], i2 = g_idx[ba+2];
    int   j0 = g_idx[ba+3], j1 = g_idx[ba+4], j2 = g_idx[ba+5];
    float u0 = g_wt[ba+0],  u1 = g_wt[ba+1],  u2 = g_wt[ba+2];
    float v0 = g_wt[ba+3],  v1 = g_wt[ba+4],  v2 = g_wt[ba+5];

    #pragma unroll
    for (int j = 0; j < 4; ++j) {
        int c = c0 + j * 64;
        const float* f = feat2 + ((size_t)b * C_ + c) * M_;
        float va = u0 * f[i0] + u1 * f[i1] + u2 * f[i2];
        float vb = v0 * f[j0] + v1 * f[j1] + v2 * f[j2];
        bf16 ha = __float2bfloat16_rn(va);
        bf16 hb = __float2bfloat16_rn(vb);
        bf16 la = __float2bfloat16_rn(va - __bfloat162float(ha));
        bf16 lb = __float2bfloat16_rn(vb - __bfloat162float(hb));
        size_t oi = ((size_t)b * C_ + c) * N_ + n;
        __nv_bfloat162 hh; hh.x = ha; hh.y = hb;
        __nv_bfloat162 ll; ll.x = la; ll.y = lb;
        *(__nv_bfloat162*)(g_interp_hi + oi) = hh;
        *(__nv_bfloat162*)(g_interp_lo + oi) = ll;
    }
}

// ---------------------------------------------------------------------------
// Kernel 3: elementwise bf16 hi/lo split (feat1, weights)
// ---------------------------------------------------------------------------
__global__ void split_kernel(const float* __restrict__ src,
                             bf16* __restrict__ hi, bf16* __restrict__ lo, int n4)
{
    int i = blockIdx.x * blockDim.x + threadIdx.x;
    if (i >= n4) return;
    float4 v = ((const float4*)src)[i];
    bf16 h0 = __float2bfloat16_rn(v.x), h1 = __float2bfloat16_rn(v.y);
    bf16 h2 = __float2bfloat16_rn(v.z), h3 = __float2bfloat16_rn(v.w);
    bf16 l0 = __float2bfloat16_rn(v.x - __bfloat162float(h0));
    bf16 l1 = __float2bfloat16_rn(v.y - __bfloat162float(h1));
    bf16 l2 = __float2bfloat16_rn(v.z - __bfloat162float(h2));
    bf16 l3 = __float2bfloat16_rn(v.w - __bfloat162float(h3));
    __nv_bfloat162 ph0; ph0.x = h0; ph0.y = h1;
    __nv_bfloat162 ph1; ph1.x = h2; ph1.y = h3;
    __nv_bfloat162 pl0; pl0.x = l0; pl0.y = l1;
    __nv_bfloat162 pl1; pl1.x = l2; pl1.y = l3;
    uint2 ph = make_uint2(*(uint32_t*)&ph0, *(uint32_t*)&ph1);
    uint2 pl = make_uint2(*(uint32_t*)&pl0, *(uint32_t*)&pl1);
    ((uint2*)hi)[i] = ph;
    ((uint2*)lo)[i] = pl;
}

// ---------------------------------------------------------------------------
// Kernel 4: bf16x3 split GEMM via mma.sync (HMMA) + BN + ReLU.
//   Y[b] = relu( (W @ X[b]) * gamma/sqrt(1+eps) + beta )
//   A = W [O,K] row-major (hi/lo bf16).  B = X [K,N] native (hi/lo bf16),
//   transposed in-register by ldmatrix.trans.  fp32 accumulate.
//   CTA tile 128x128, BK=32, 8 warps (2x4), warp tile 64x32,
//   double-buffered cp.async pipeline.
// ---------------------------------------------------------------------------
#define A_ROW   80u            // 32 bf16 = 64B data + 16B pad (bank spread)
#define B_ROW   272u           // 128 bf16 = 256B data + 16B pad
#define OFF_AH  0u
#define OFF_AL  10240u         // 128*80
#define OFF_BH  20480u
#define OFF_BL  29184u         // +32*272
#define STAGE   37888u

__global__ __launch_bounds__(256)
void bf16_gemm(const bf16* __restrict__ Whi, const bf16* __restrict__ Wlo,
               const bf16* __restrict__ X0hi, const bf16* __restrict__ X0lo,
               const bf16* __restrict__ X1hi, const bf16* __restrict__ X1lo,
               const float* __restrict__ gamma, const float* __restrict__ beta,
               float* __restrict__ Yf, bf16* __restrict__ Yh, bf16* __restrict__ Yl,
               int K, int Ksplit, int split_out)
{
    extern __shared__ char smem_raw[];
    const uint32_t sm = smem_u32(smem_raw);
    const int tid  = threadIdx.x;
    const int lane = tid & 31, wid = tid >> 5;
    const int wm = wid >> 2, wn = wid & 3;
    const int bn = blockIdx.x * 128, bo = blockIdx.y * 128, b = blockIdx.z;

    const size_t xs = (size_t)C_ * N_;
    const bf16* x0h = X0hi + (size_t)b * xs;
    const bf16* x0l = X0lo + (size_t)b * xs;
    const bf16* x1h = X1hi + (size_t)b * xs;
    const bf16* x1l = X1lo + (size_t)b * xs;

    auto prefetch = [&](int s) {
        const uint32_t buf = sm + (uint32_t)(s & 1) * STAGE;
        const int kt = s * 32;
        #pragma unroll
        for (int i = 0; i < 2; i++) {           // A: 128 rows x 4 chunks
            int idx = i * 256 + tid;
            int row = idx >> 2, ch = idx & 3;
            size_t go = (size_t)(bo + row) * K + kt + ch * 8;
            uint32_t so = row * A_ROW + ch * 16;
            cp16(buf + OFF_AH + so, Whi + go);
            cp16(buf + OFF_AL + so, Wlo + go);
        }
        #pragma unroll
        for (int i = 0; i < 2; i++) {           // B: 32 k-rows x 16 chunks
            int idx = i * 256 + tid;
            int kr = idx >> 4, ch = idx & 15;
            int kg = kt + kr;
            const bf16 *sh_, *sl_; size_t roff;
            if (kg < Ksplit) { sh_ = x0h; sl_ = x0l; roff = (size_t)kg * N_; }
            else             { sh_ = x1h; sl_ = x1l; roff = (size_t)(kg - Ksplit) * N_; }
            uint32_t so = kr * B_ROW + ch * 16;
            cp16(buf + OFF_BH + so, sh_ + roff + bn + ch * 8);
            cp16(buf + OFF_BL + so, sl_ + roff + bn + ch * 8);
        }
        asm volatile("cp.async.commit_group;" ::: "memory");
    };

    float acc[4][4][4];
    #pragma unroll
    for (int i = 0; i < 4; i++)
        #pragma unroll
        for (int j = 0; j < 4; j++)
            #pragma unroll
            for (int k = 0; k < 4; k++) acc[i][j][k] = 0.0f;

    const int nst = K / 32;
    prefetch(0);

    for (int s = 0; s < nst; s++) {
        if (s + 1 < nst) {
            prefetch(s + 1);
            asm volatile("cp.async.wait_group 1;" ::: "memory");
        } else {
            asm volatile("cp.async.wait_group 0;" ::: "memory");
        }
        __syncthreads();

        const uint32_t buf = sm + (uint32_t)(s & 1) * STAGE;
        #pragma unroll
        for (int ks = 0; ks < 2; ks++) {
            uint32_t Af[2][4][4], Bf[2][4][2];
            // A fragments: lanes 0-15 -> rows m0-15 (k-half 0), 16-31 -> k-half 1
            const uint32_t arow = wm * 64 + (lane & 15);
            const uint32_t ach  = (uint32_t)(ks * 2) + (lane >> 4);
            #pragma unroll
            for (int mf = 0; mf < 4; mf++) {
                uint32_t off = (arow + mf * 16) * A_ROW + ach * 16;
                ldsm4(Af[0][mf], buf + OFF_AH + off);
                ldsm4(Af[1][mf], buf + OFF_AL + off);
            }
            // B fragments (trans): k = ks*16 + octet, ncol stepped by lane>>4
            const uint32_t bk = (uint32_t)(ks * 16) + ((lane >> 3) & 1) * 8 + (lane & 7);
            #pragma unroll
            for (int g = 0; g < 2; g++) {
                uint32_t ncol = wn * 32 + g * 16 + (lane >> 4) * 8;
                uint32_t off  = bk * B_ROW + ncol * 2;
                uint32_t r[4];
                ldsm4t(r, buf + OFF_BH + off);
                Bf[0][g*2][0] = r[0]; Bf[0][g*2][1] = r[1];
                Bf[0][g*2+1][0] = r[2]; Bf[0][g*2+1][1] = r[3];
                ldsm4t(r, buf + OFF_BL + off);
                Bf[1][g*2][0] = r[0]; Bf[1][g*2][1] = r[1];
                Bf[1][g*2+1][0] = r[2]; Bf[1][g*2+1][1] = r[3];
            }
            // 3 terms: hi*hi, hi*lo, lo*hi
            #pragma unroll
            for (int mf = 0; mf < 4; mf++)
                #pragma unroll
                for (int nf = 0; nf < 4; nf++)
                    mma_bf16(acc[mf][nf], Af[0][mf], Bf[0][nf]);
            #pragma unroll
            for (int mf = 0; mf < 4; mf++)
                #pragma unroll
                for (int nf = 0; nf < 4; nf++)
                    mma_bf16(acc[mf][nf], Af[0][mf], Bf[1][nf]);
            #pragma unroll
            for (int mf = 0; mf < 4; mf++)
                #pragma unroll
                for (int nf = 0; nf < 4; nf++)
                    mma_bf16(acc[mf][nf], Af[1][mf], Bf[0][nf]);
        }
        __syncthreads();
    }

    // Epilogue.  Accum frag (mf,nf): rows = wm*64+mf*16+grp (+8),
    // cols = wn*32+nf*8+qid*2 (+1).
    const int grp = lane >> 2, qid = lane & 3;
    const float bninv = 0.9999950000374997f;  // 1/sqrt(1+1e-5)
    #pragma unroll
    for (int mf = 0; mf < 4; mf++) {
        #pragma unroll
        for (int h = 0; h < 2; h++) {
            int o = bo + wm * 64 + mf * 16 + grp + h * 8;
            float g  = gamma[o] * bninv;
            float bt = beta[o];
            size_t yrow = ((size_t)b * C_ + o) * N_ + bn + wn * 32 + qid * 2;
            #pragma unroll
            for (int nf = 0; nf < 4; nf++) {
                float v0 = fmaxf(fmaf(acc[mf][nf][h*2+0], g, bt), 0.0f);
                float v1 = fmaxf(fmaf(acc[mf][nf][h*2+1], g, bt), 0.0f);
                size_t yo = yrow + nf * 8;
                if (split_out) {
                    bf16 h0 = __float2bfloat16_rn(v0);
                    bf16 h1 = __float2bfloat16_rn(v1);
                    bf16 l0 = __float2bfloat16_rn(v0 - __bfloat162float(h0));
                    bf16 l1 = __float2bfloat16_rn(v1 - __bfloat162float(h1));
                    __nv_bfloat162 hh; hh.x = h0; hh.y = h1;
                    __nv_bfloat162 ll; ll.x = l0; ll.y = l1;
                    *(uint32_t*)(Yh + yo) = *(uint32_t*)&hh;
                    *(uint32_t*)(Yl + yo) = *(uint32_t*)&ll;
                } else {
                    *(float2*)(Yf + yo) = make_float2(v0, v1);
                }
            }
        }
    }
}

// ---------------------------------------------------------------------------
extern "C" void kernel_launch(void* const* d_in, const int* in_sizes, int n_in,
                              void* d_out, int out_size)
{
    const float* xyz1   = (const float*)d_in[0];
    const float* xyz2   = (const float*)d_in[1];
    const float* feat1  = (const float*)d_in[2];
    const float* feat2  = (const float*)d_in[3];
    const float* w1     = (const float*)d_in[4];
    const float* gamma1 = (const float*)d_in[5];
    const float* beta1  = (const float*)d_in[6];
    const float* w2     = (const float*)d_in[7];
    const float* gamma2 = (const float*)d_in[8];
    const float* beta2  = (const float*)d_in[9];
    float* out = (float*)d_out;

    bf16 *ih, *il, *f1h, *f1l, *h1h, *h1l, *w1h, *w1l, *w2h, *w2l;
    cudaGetSymbolAddress((void**)&ih,  g_interp_hi);
    cudaGetSymbolAddress((void**)&il,  g_interp_lo);
    cudaGetSymbolAddress((void**)&f1h, g_feat1_hi);
    cudaGetSymbolAddress((void**)&f1l, g_feat1_lo);
    cudaGetSymbolAddress((void**)&h1h, g_h1_hi);
    cudaGetSymbolAddress((void**)&h1l, g_h1_lo);
    cudaGetSymbolAddress((void**)&w1h, g_w1_hi);
    cudaGetSymbolAddress((void**)&w1l, g_w1_lo);
    cudaGetSymbolAddress((void**)&w2h, g_w2_hi);
    cudaGetSymbolAddress((void**)&w2l, g_w2_lo);

    const int SMEM_BYTES = 2 * STAGE;   // 75776
    cudaFuncSetAttribute(bf16_gemm, cudaFuncAttributeMaxDynamicSharedMemorySize,
                         SMEM_BYTES);

    dim3 gknn(N_ / 256, B_);
    knn_kernel<<<gknn, 256>>>(xyz1, xyz2);

    dim3 gint(N_ / 512, 64, B_);
    interp_kernel<<<gint, 256>>>(feat2);

    split_kernel<<<(B_ * C_ * N_ / 4 + 255) / 256, 256>>>(feat1, f1h, f1l,
                                                          B_ * C_ * N_ / 4);
    split_kernel<<<(C_ * KIN / 4 + 255) / 256, 256>>>(w1, w1h, w1l, C_ * KIN / 4);
    split_kernel<<<(C_ * C_ / 4 + 255) / 256, 256>>>(w2, w2h, w2l, C_ * C_ / 4);

    dim3 gg(N_ / 128, C_ / 128, B_);
    // GEMM1: K=512; B rows <256 from interp, >=256 from feat1; bf16 split output
    bf16_gemm<<<gg, 256, SMEM_BYTES>>>(w1h, w1l, ih, il, f1h, f1l,
                                       gamma1, beta1, (float*)0, h1h, h1l,
                                       KIN, C_, 1);
    // GEMM2: K=256; fp32 output to d_out
    bf16_gemm<<<gg, 256, SMEM_BYTES>>>(w2h, w2l, h1h, h1l, h1h, h1l,
                                       gamma2, beta2, out, (bf16*)0, (bf16*)0,
                                       C_, C_, 0);
}

// round 5
// speedup vs baseline: 2.2529x; 1.0446x over previous
#include <cuda_runtime.h>
#include <cuda_bf16.h>
#include <cstdint>
#include <cstddef>

#define B_  16
#define N_  4096
#define M_  1024
#define C_  256
#define KIN 512

typedef __nv_bfloat16 bf16;

// ---------------------------------------------------------------------------
// Scratch (static device globals; allocation is forbidden in kernel_launch)
// ---------------------------------------------------------------------------
__device__ __align__(16) bf16 g_interp_hi[(size_t)B_ * C_ * N_];
__device__ __align__(16) bf16 g_interp_lo[(size_t)B_ * C_ * N_];
__device__ __align__(16) bf16 g_feat1_hi[(size_t)B_ * C_ * N_];
__device__ __align__(16) bf16 g_feat1_lo[(size_t)B_ * C_ * N_];
__device__ __align__(16) bf16 g_h1_hi[(size_t)B_ * C_ * N_];
__device__ __align__(16) bf16 g_h1_lo[(size_t)B_ * C_ * N_];
__device__ __align__(16) bf16 g_w1_hi[C_ * KIN], g_w1_lo[C_ * KIN];
__device__ __align__(16) bf16 g_w2_hi[C_ * C_],  g_w2_lo[C_ * C_];
__device__ int   g_idx[B_ * N_ * 3];
__device__ float g_wt[B_ * N_ * 3];

// ---------------------------------------------------------------------------
// PTX helpers (architecture-portable: sm_80+ instructions only)
// ---------------------------------------------------------------------------
static __device__ __forceinline__ uint32_t smem_u32(const void* p) {
    uint32_t a;
    asm("{ .reg .u64 t; cvta.to.shared.u64 t, %1; cvt.u32.u64 %0, t; }"
        : "=r"(a) : "l"(p));
    return a;
}
static __device__ __forceinline__ void cp16(uint32_t s, const void* g) {
    asm volatile("cp.async.cg.shared.global [%0], [%1], 16;" :: "r"(s), "l"(g));
}
static __device__ __forceinline__ void ldsm4(uint32_t* r, uint32_t a) {
    asm volatile("ldmatrix.sync.aligned.m8n8.x4.shared.b16 {%0,%1,%2,%3}, [%4];"
                 : "=r"(r[0]), "=r"(r[1]), "=r"(r[2]), "=r"(r[3]) : "r"(a));
}
static __device__ __forceinline__ void ldsm4t(uint32_t* r, uint32_t a) {
    asm volatile("ldmatrix.sync.aligned.m8n8.x4.trans.shared.b16 {%0,%1,%2,%3}, [%4];"
                 : "=r"(r[0]), "=r"(r[1]), "=r"(r[2]), "=r"(r[3]) : "r"(a));
}
static __device__ __forceinline__ void mma_bf16(float* c, const uint32_t* a,
                                                const uint32_t* b) {
    asm volatile(
        "mma.sync.aligned.m16n8k16.row.col.f32.bf16.bf16.f32 "
        "{%0,%1,%2,%3}, {%4,%5,%6,%7}, {%8,%9}, {%0,%1,%2,%3};"
        : "+f"(c[0]), "+f"(c[1]), "+f"(c[2]), "+f"(c[3])
        : "r"(a[0]), "r"(a[1]), "r"(a[2]), "r"(a[3]), "r"(b[0]), "r"(b[1]));
}

// ---------------------------------------------------------------------------
// Kernel 1: 3-NN (unchanged — verified correct)
// ---------------------------------------------------------------------------
__global__ void knn_kernel(const float* __restrict__ xyz1,
                           const float* __restrict__ xyz2)
{
    __shared__ float4 sp[256];
    const int tid = threadIdx.x;
    const int b   = blockIdx.y;
    const int n   = blockIdx.x * 256 + tid;

    const float* p1 = xyz1 + ((size_t)b * N_ + n) * 3;
    const float px = p1[0], py = p1[1], pz = p1[2];
    const float s1 = px * px + py * py + pz * pz;

    float b0 = 3.4e38f, b1 = 3.4e38f, b2 = 3.4e38f;
    int   i0 = 0, i1 = 0, i2 = 0;

    for (int mt = 0; mt < M_; mt += 256) {
        const float* p2 = xyz2 + ((size_t)b * M_ + mt + tid) * 3;
        float x = p2[0], y = p2[1], z = p2[2];
        __syncthreads();
        sp[tid] = make_float4(x, y, z, x * x + y * y + z * z);
        __syncthreads();
        #pragma unroll 8
        for (int j = 0; j < 256; ++j) {
            float4 q = sp[j];
            float dot = px * q.x + py * q.y + pz * q.z;
            float d2  = (s1 + q.w) - 2.0f * dot;
            int   m   = mt + j;
            if (d2 < b2) {
                if (d2 < b1) {
                    if (d2 < b0) { b2 = b1; i2 = i1; b1 = b0; i1 = i0; b0 = d2; i0 = m; }
                    else         { b2 = b1; i2 = i1; b1 = d2; i1 = m; }
                } else           { b2 = d2; i2 = m; }
            }
        }
    }

    float w0 = 1.0f / (b0 + 1e-8f);
    float w1 = 1.0f / (b1 + 1e-8f);
    float w2 = 1.0f / (b2 + 1e-8f);
    float ws = w0 + w1 + w2;

    size_t base = ((size_t)b * N_ + n) * 3;
    g_idx[base + 0] = i0; g_idx[base + 1] = i1; g_idx[base + 2] = i2;
    g_wt[base + 0] = w0 / ws; g_wt[base + 1] = w1 / ws; g_wt[base + 2] = w2 / ws;
}

// ---------------------------------------------------------------------------
// Kernel 2: weighted 3-point gather -> interp (bf16 hi/lo), unchanged
// ---------------------------------------------------------------------------
__global__ void interp_kernel(const float* __restrict__ feat2)
{
    const int tid = threadIdx.x;
    const int n   = (blockIdx.x * 256 + tid) * 2;
    const int c0  = blockIdx.y;          // 0..63
    const int b   = blockIdx.z;

    size_t ba = ((size_t)b * N_ + n) * 3;
    int   i0 = g_idx[ba+0], i1 = g_idx[ba+1], i2 = g_idx[ba+2];
    int   j0 = g_idx[ba+3], j1 = g_idx[ba+4], j2 = g_idx[ba+5];
    float u0 = g_wt[ba+0],  u1 = g_wt[ba+1],  u2 = g_wt[ba+2];
    float v0 = g_wt[ba+3],  v1 = g_wt[ba+4],  v2 = g_wt[ba+5];

    #pragma unroll
    for (int j = 0; j < 4; ++j) {
        int c = c0 + j * 64;
        const float* f = feat2 + ((size_t)b * C_ + c) * M_;
        float va = u0 * f[i0] + u1 * f[i1] + u2 * f[i2];
        float vb = v0 * f[j0] + v1 * f[j1] + v2 * f[j2];
        bf16 ha = __float2bfloat16_rn(va);
        bf16 hb = __float2bfloat16_rn(vb);
        bf16 la = __float2bfloat16_rn(va - __bfloat162float(ha));
        bf16 lb = __float2bfloat16_rn(vb - __bfloat162float(hb));
        size_t oi = ((size_t)b * C_ + c) * N_ + n;
        __nv_bfloat162 hh; hh.x = ha; hh.y = hb;
        __nv_bfloat162 ll; ll.x = la; ll.y = lb;
        *(__nv_bfloat162*)(g_interp_hi + oi) = hh;
        *(__nv_bfloat162*)(g_interp_lo + oi) = ll;
    }
}

// ---------------------------------------------------------------------------
// Kernel 3: elementwise bf16 hi/lo split (feat1, weights), unchanged
// ---------------------------------------------------------------------------
__global__ void split_kernel(const float* __restrict__ src,
                             bf16* __restrict__ hi, bf16* __restrict__ lo, int n4)
{
    int i = blockIdx.x * blockDim.x + threadIdx.x;
    if (i >= n4) return;
    float4 v = ((const float4*)src)[i];
    bf16 h0 = __float2bfloat16_rn(v.x), h1 = __float2bfloat16_rn(v.y);
    bf16 h2 = __float2bfloat16_rn(v.z), h3 = __float2bfloat16_rn(v.w);
    bf16 l0 = __float2bfloat16_rn(v.x - __bfloat162float(h0));
    bf16 l1 = __float2bfloat16_rn(v.y - __bfloat162float(h1));
    bf16 l2 = __float2bfloat16_rn(v.z - __bfloat162float(h2));
    bf16 l3 = __float2bfloat16_rn(v.w - __bfloat162float(h3));
    __nv_bfloat162 ph0; ph0.x = h0; ph0.y = h1;
    __nv_bfloat162 ph1; ph1.x = h2; ph1.y = h3;
    __nv_bfloat162 pl0; pl0.x = l0; pl0.y = l1;
    __nv_bfloat162 pl1; pl1.x = l2; pl1.y = l3;
    uint2 ph = make_uint2(*(uint32_t*)&ph0, *(uint32_t*)&ph1);
    uint2 pl = make_uint2(*(uint32_t*)&pl0, *(uint32_t*)&pl1);
    ((uint2*)hi)[i] = ph;
    ((uint2*)lo)[i] = pl;
}

// ---------------------------------------------------------------------------
// Kernel 4: bf16x3 split GEMM via mma.sync + BN + ReLU.
//   R5 changes: __launch_bounds__(256, 2) for 2 CTAs/SM, and B-fragment
//   registers reused between the hi and lo terms to keep peak liveness
//   ~115 regs (acc 64 + A 32 + B 8 + addressing) under the 128 cap.
// ---------------------------------------------------------------------------
#define A_ROW   80u            // 32 bf16 = 64B data + 16B pad
#define B_ROW   272u           // 128 bf16 = 256B data + 16B pad
#define OFF_AH  0u
#define OFF_AL  10240u         // 128*80
#define OFF_BH  20480u
#define OFF_BL  29184u         // +32*272
#define STAGE   37888u

__global__ __launch_bounds__(256, 2)
void bf16_gemm(const bf16* __restrict__ Whi, const bf16* __restrict__ Wlo,
               const bf16* __restrict__ X0hi, const bf16* __restrict__ X0lo,
               const bf16* __restrict__ X1hi, const bf16* __restrict__ X1lo,
               const float* __restrict__ gamma, const float* __restrict__ beta,
               float* __restrict__ Yf, bf16* __restrict__ Yh, bf16* __restrict__ Yl,
               int K, int Ksplit, int split_out)
{
    extern __shared__ char smem_raw[];
    const uint32_t sm = smem_u32(smem_raw);
    const int tid  = threadIdx.x;
    const int lane = tid & 31, wid = tid >> 5;
    const int wm = wid >> 2, wn = wid & 3;
    const int bn = blockIdx.x * 128, bo = blockIdx.y * 128, b = blockIdx.z;

    const size_t xs = (size_t)C_ * N_;
    const bf16* x0h = X0hi + (size_t)b * xs;
    const bf16* x0l = X0lo + (size_t)b * xs;
    const bf16* x1h = X1hi + (size_t)b * xs;
    const bf16* x1l = X1lo + (size_t)b * xs;

    auto prefetch = [&](int s) {
        const uint32_t buf = sm + (uint32_t)(s & 1) * STAGE;
        const int kt = s * 32;
        #pragma unroll
        for (int i = 0; i < 2; i++) {           // A: 128 rows x 4 chunks
            int idx = i * 256 + tid;
            int row = idx >> 2, ch = idx & 3;
            size_t go = (size_t)(bo + row) * K + kt + ch * 8;
            uint32_t so = row * A_ROW + ch * 16;
            cp16(buf + OFF_AH + so, Whi + go);
            cp16(buf + OFF_AL + so, Wlo + go);
        }
        #pragma unroll
        for (int i = 0; i < 2; i++) {           // B: 32 k-rows x 16 chunks
            int idx = i * 256 + tid;
            int kr = idx >> 4, ch = idx & 15;
            int kg = kt + kr;
            const bf16 *sh_, *sl_; size_t roff;
            if (kg < Ksplit) { sh_ = x0h; sl_ = x0l; roff = (size_t)kg * N_; }
            else             { sh_ = x1h; sl_ = x1l; roff = (size_t)(kg - Ksplit) * N_; }
            uint32_t so = kr * B_ROW + ch * 16;
            cp16(buf + OFF_BH + so, sh_ + roff + bn + ch * 8);
            cp16(buf + OFF_BL + so, sl_ + roff + bn + ch * 8);
        }
        asm volatile("cp.async.commit_group;" ::: "memory");
    };

    float acc[4][4][4];
    #pragma unroll
    for (int i = 0; i < 4; i++)
        #pragma unroll
        for (int j = 0; j < 4; j++)
            #pragma unroll
            for (int k = 0; k < 4; k++) acc[i][j][k] = 0.0f;

    const int nst = K / 32;
    prefetch(0);

    for (int s = 0; s < nst; s++) {
        if (s + 1 < nst) {
            prefetch(s + 1);
            asm volatile("cp.async.wait_group 1;" ::: "memory");
        } else {
            asm volatile("cp.async.wait_group 0;" ::: "memory");
        }
        __syncthreads();

        const uint32_t buf = sm + (uint32_t)(s & 1) * STAGE;
        #pragma unroll
        for (int ks = 0; ks < 2; ks++) {
            uint32_t Afh[4][4], Afl[4][4], Bfr[4][2];
            // A fragments: lanes 0-15 -> rows m0-15 (k-half 0), 16-31 -> k-half 1
            const uint32_t arow = wm * 64 + (lane & 15);
            const uint32_t ach  = (uint32_t)(ks * 2) + (lane >> 4);
            #pragma unroll
            for (int mf = 0; mf < 4; mf++) {
                uint32_t off = (arow + mf * 16) * A_ROW + ach * 16;
                ldsm4(Afh[mf], buf + OFF_AH + off);
                ldsm4(Afl[mf], buf + OFF_AL + off);
            }
            // B hi fragments (trans)
            const uint32_t bk = (uint32_t)(ks * 16) + ((lane >> 3) & 1) * 8 + (lane & 7);
            #pragma unroll
            for (int g = 0; g < 2; g++) {
                uint32_t ncol = wn * 32 + g * 16 + (lane >> 4) * 8;
                uint32_t off  = bk * B_ROW + ncol * 2;
                uint32_t r[4];
                ldsm4t(r, buf + OFF_BH + off);
                Bfr[g*2][0] = r[0]; Bfr[g*2][1] = r[1];
                Bfr[g*2+1][0] = r[2]; Bfr[g*2+1][1] = r[3];
            }
            // hi*hi and lo*hi while only B-hi is live
            #pragma unroll
            for (int mf = 0; mf < 4; mf++)
                #pragma unroll
                for (int nf = 0; nf < 4; nf++)
                    mma_bf16(acc[mf][nf], Afh[mf], Bfr[nf]);
            #pragma unroll
            for (int mf = 0; mf < 4; mf++)
                #pragma unroll
                for (int nf = 0; nf < 4; nf++)
                    mma_bf16(acc[mf][nf], Afl[mf], Bfr[nf]);
            // overwrite B regs with B-lo, then hi*lo
            #pragma unroll
            for (int g = 0; g < 2; g++) {
                uint32_t ncol = wn * 32 + g * 16 + (lane >> 4) * 8;
                uint32_t off  = bk * B_ROW + ncol * 2;
                uint32_t r[4];
                ldsm4t(r, buf + OFF_BL + off);
                Bfr[g*2][0] = r[0]; Bfr[g*2][1] = r[1];
                Bfr[g*2+1][0] = r[2]; Bfr[g*2+1][1] = r[3];
            }
            #pragma unroll
            for (int mf = 0; mf < 4; mf++)
                #pragma unroll
                for (int nf = 0; nf < 4; nf++)
                    mma_bf16(acc[mf][nf], Afh[mf], Bfr[nf]);
        }
        __syncthreads();
    }

    // Epilogue.  Accum frag (mf,nf): rows = wm*64+mf*16+grp (+8),
    // cols = wn*32+nf*8+qid*2 (+1).
    const int grp = lane >> 2, qid = lane & 3;
    const float bninv = 0.9999950000374997f;  // 1/sqrt(1+1e-5)
    #pragma unroll
    for (int mf = 0; mf < 4; mf++) {
        #pragma unroll
        for (int h = 0; h < 2; h++) {
            int o = bo + wm * 64 + mf * 16 + grp + h * 8;
            float g  = gamma[o] * bninv;
            float bt = beta[o];
            size_t yrow = ((size_t)b * C_ + o) * N_ + bn + wn * 32 + qid * 2;
            #pragma unroll
            for (int nf = 0; nf < 4; nf++) {
                float v0 = fmaxf(fmaf(acc[mf][nf][h*2+0], g, bt), 0.0f);
                float v1 = fmaxf(fmaf(acc[mf][nf][h*2+1], g, bt), 0.0f);
                size_t yo = yrow + nf * 8;
                if (split_out) {
                    bf16 h0 = __float2bfloat16_rn(v0);
                    bf16 h1 = __float2bfloat16_rn(v1);
                    bf16 l0 = __float2bfloat16_rn(v0 - __bfloat162float(h0));
                    bf16 l1 = __float2bfloat16_rn(v1 - __bfloat162float(h1));
                    __nv_bfloat162 hh; hh.x = h0; hh.y = h1;
                    __nv_bfloat162 ll; ll.x = l0; ll.y = l1;
                    *(uint32_t*)(Yh + yo) = *(uint32_t*)&hh;
                    *(uint32_t*)(Yl + yo) = *(uint32_t*)&ll;
                } else {
                    *(float2*)(Yf + yo) = make_float2(v0, v1);
                }
            }
        }
    }
}

// ---------------------------------------------------------------------------
extern "C" void kernel_launch(void* const* d_in, const int* in_sizes, int n_in,
                              void* d_out, int out_size)
{
    const float* xyz1   = (const float*)d_in[0];
    const float* xyz2   = (const float*)d_in[1];
    const float* feat1  = (const float*)d_in[2];
    const float* feat2  = (const float*)d_in[3];
    const float* w1     = (const float*)d_in[4];
    const float* gamma1 = (const float*)d_in[5];
    const float* beta1  = (const float*)d_in[6];
    const float* w2     = (const float*)d_in[7];
    const float* gamma2 = (const float*)d_in[8];
    const float* beta2  = (const float*)d_in[9];
    float* out = (float*)d_out;

    bf16 *ih, *il, *f1h, *f1l, *h1h, *h1l, *w1h, *w1l, *w2h, *w2l;
    cudaGetSymbolAddress((void**)&ih,  g_interp_hi);
    cudaGetSymbolAddress((void**)&il,  g_interp_lo);
    cudaGetSymbolAddress((void**)&f1h, g_feat1_hi);
    cudaGetSymbolAddress((void**)&f1l, g_feat1_lo);
    cudaGetSymbolAddress((void**)&h1h, g_h1_hi);
    cudaGetSymbolAddress((void**)&h1l, g_h1_lo);
    cudaGetSymbolAddress((void**)&w1h, g_w1_hi);
    cudaGetSymbolAddress((void**)&w1l, g_w1_lo);
    cudaGetSymbolAddress((void**)&w2h, g_w2_hi);
    cudaGetSymbolAddress((void**)&w2l, g_w2_lo);

    const int SMEM_BYTES = 2 * STAGE;   // 75776
    cudaFuncSetAttribute(bf16_gemm, cudaFuncAttributeMaxDynamicSharedMemorySize,
                         SMEM_BYTES);

    // Launch order chosen so ncu's "-s 5 -c 1" captures GEMM1 (launch index 5):
    // 0:split(w1) 1:split(w2) 2:split(feat1) 3:knn 4:interp 5:gemm1 6:gemm2
    split_kernel<<<(C_ * KIN / 4 + 255) / 256, 256>>>(w1, w1h, w1l, C_ * KIN / 4);
    split_kernel<<<(C_ * C_ / 4 + 255) / 256, 256>>>(w2, w2h, w2l, C_ * C_ / 4);
    split_kernel<<<(B_ * C_ * N_ / 4 + 255) / 256, 256>>>(feat1, f1h, f1l,
                                                          B_ * C_ * N_ / 4);

    dim3 gknn(N_ / 256, B_);
    knn_kernel<<<gknn, 256>>>(xyz1, xyz2);

    dim3 gint(N_ / 512, 64, B_);
    interp_kernel<<<gint, 256>>>(feat2);

    dim3 gg(N_ / 128, C_ / 128, B_);
    // GEMM1: K=512; B rows <256 from interp, >=256 from feat1; bf16 split output
    bf16_gemm<<<gg, 256, SMEM_BYTES>>>(w1h, w1l, ih, il, f1h, f1l,
                                       gamma1, beta1, (float*)0, h1h, h1l,
                                       KIN, C_, 1);
    // GEMM2: K=256; fp32 output to d_out
    bf16_gemm<<<gg, 256, SMEM_BYTES>>>(w2h, w2l, h1h, h1l, h1h, h1l,
                                       gamma2, beta2, out, (bf16*)0, (bf16*)0,
                                       C_, C_, 0);
}

// round 7
// speedup vs baseline: 2.6746x; 1.1872x over previous
#include <cuda_runtime.h>
#include <cuda_fp16.h>
#include <cstdint>
#include <cstddef>

#define B_  16
#define N_  4096
#define M_  1024
#define C_  256
#define KIN 512

// ---------------------------------------------------------------------------
// Scratch (static device globals; allocation is forbidden in kernel_launch)
// ---------------------------------------------------------------------------
__device__ __align__(16) __half g_interp_h[(size_t)B_ * C_ * N_];
__device__ __align__(16) __half g_feat1_h[(size_t)B_ * C_ * N_];
__device__ __align__(16) __half g_h1_h[(size_t)B_ * C_ * N_];
__device__ __align__(16) __half g_w1_h[C_ * KIN];
__device__ __align__(16) __half g_w2_h[C_ * C_];
__device__ int   g_idx[B_ * N_ * 3];
__device__ float g_wt[B_ * N_ * 3];

// ---------------------------------------------------------------------------
// PTX helpers (architecture-portable: sm_80+ instructions only)
// ---------------------------------------------------------------------------
static __device__ __forceinline__ uint32_t smem_u32(const void* p) {
    uint32_t a;
    asm("{ .reg .u64 t; cvta.to.shared.u64 t, %1; cvt.u32.u64 %0, t; }"
        : "=r"(a) : "l"(p));
    return a;
}
static __device__ __forceinline__ void cp16(uint32_t s, const void* g) {
    asm volatile("cp.async.cg.shared.global [%0], [%1], 16;" :: "r"(s), "l"(g));
}
static __device__ __forceinline__ void ldsm4(uint32_t* r, uint32_t a) {
    asm volatile("ldmatrix.sync.aligned.m8n8.x4.shared.b16 {%0,%1,%2,%3}, [%4];"
                 : "=r"(r[0]), "=r"(r[1]), "=r"(r[2]), "=r"(r[3]) : "r"(a));
}
static __device__ __forceinline__ void ldsm4t(uint32_t* r, uint32_t a) {
    asm volatile("ldmatrix.sync.aligned.m8n8.x4.trans.shared.b16 {%0,%1,%2,%3}, [%4];"
                 : "=r"(r[0]), "=r"(r[1]), "=r"(r[2]), "=r"(r[3]) : "r"(a));
}
static __device__ __forceinline__ void mma_f16(float* c, const uint32_t* a,
                                               const uint32_t* b) {
    asm volatile(
        "mma.sync.aligned.m16n8k16.row.col.f32.f16.f16.f32 "
        "{%0,%1,%2,%3}, {%4,%5,%6,%7}, {%8,%9}, {%0,%1,%2,%3};"
        : "+f"(c[0]), "+f"(c[1]), "+f"(c[2]), "+f"(c[3])
        : "r"(a[0]), "r"(a[1]), "r"(a[2]), "r"(a[3]), "r"(b[0]), "r"(b[1]));
}

// ---------------------------------------------------------------------------
// Kernel 1: 3-NN, 4-way split.  64 queries/CTA, 4 lanes per query each
// scanning a disjoint 256-candidate range, then a shfl_xor butterfly merge.
// Lexicographic (d, idx) ordering preserves top_k's lowest-index tie-break.
// ---------------------------------------------------------------------------
__global__ void knn_kernel(const float* __restrict__ xyz1,
                           const float* __restrict__ xyz2)
{
    __shared__ float4 sp[1024];
    const int tid = threadIdx.x;
    const int b   = blockIdx.y;
    const int p   = tid & 3;             // candidate-range part
    const int n   = blockIdx.x * 64 + (tid >> 2);

    // stage all 1024 candidates
    for (int i = tid; i < M_; i += 256) {
        const float* p2 = xyz2 + ((size_t)b * M_ + i) * 3;
        float x = p2[0], y = p2[1], z = p2[2];
        sp[i] = make_float4(x, y, z, x * x + y * y + z * z);
    }

    const float* p1 = xyz1 + ((size_t)b * N_ + n) * 3;
    const float px = p1[0], py = p1[1], pz = p1[2];
    const float s1 = px * px + py * py + pz * pz;
    __syncthreads();

    float b0 = 3.4e38f, b1 = 3.4e38f, b2 = 3.4e38f;
    int   i0 = 0, i1 = 0, i2 = 0;

    const int base = p * 256;
    #pragma unroll 8
    for (int j = 0; j < 256; ++j) {
        float4 q = sp[base + j];
        float dot = px * q.x + py * q.y + pz * q.z;
        float d2  = (s1 + q.w) - 2.0f * dot;
        int   m   = base + j;
        if (d2 < b2) {
            if (d2 < b1) {
                if (d2 < b0) { b2 = b1; i2 = i1; b1 = b0; i1 = i0; b0 = d2; i0 = m; }
                else         { b2 = b1; i2 = i1; b1 = d2; i1 = m; }
            } else           { b2 = d2; i2 = m; }
        }
    }

    // butterfly merge across the 4 lanes of this query
    #pragma unroll
    for (int off = 1; off <= 2; off <<= 1) {
        float c0 = __shfl_xor_sync(0xFFFFFFFFu, b0, off);
        float c1 = __shfl_xor_sync(0xFFFFFFFFu, b1, off);
        float c2 = __shfl_xor_sync(0xFFFFFFFFu, b2, off);
        int   j0 = __shfl_xor_sync(0xFFFFFFFFu, i0, off);
        int   j1 = __shfl_xor_sync(0xFFFFFFFFu, i1, off);
        int   j2 = __shfl_xor_sync(0xFFFFFFFFu, i2, off);
        #pragma unroll
        for (int e = 0; e < 3; ++e) {
            float d = (e == 0) ? c0 : (e == 1) ? c1 : c2;
            int   m = (e == 0) ? j0 : (e == 1) ? j1 : j2;
            bool l2 = (d < b2) || (d == b2 && m < i2);
            if (l2) {
                bool l1 = (d < b1) || (d == b1 && m < i1);
                if (l1) {
                    bool l0 = (d < b0) || (d == b0 && m < i0);
                    if (l0) { b2 = b1; i2 = i1; b1 = b0; i1 = i0; b0 = d; i0 = m; }
                    else    { b2 = b1; i2 = i1; b1 = d; i1 = m; }
                } else      { b2 = d; i2 = m; }
            }
        }
    }

    if (p == 0) {
        float w0 = 1.0f / (b0 + 1e-8f);
        float w1 = 1.0f / (b1 + 1e-8f);
        float w2 = 1.0f / (b2 + 1e-8f);
        float ws = w0 + w1 + w2;
        size_t base2 = ((size_t)b * N_ + n) * 3;
        g_idx[base2 + 0] = i0; g_idx[base2 + 1] = i1; g_idx[base2 + 2] = i2;
        g_wt[base2 + 0] = w0 / ws; g_wt[base2 + 1] = w1 / ws; g_wt[base2 + 2] = w2 / ws;
    }
}

// ---------------------------------------------------------------------------
// Kernel 2: weighted 3-point gather -> interp as fp16
// ---------------------------------------------------------------------------
__global__ void interp_kernel(const float* __restrict__ feat2)
{
    const int tid = threadIdx.x;
    const int n   = (blockIdx.x * 256 + tid) * 2;
    const int c0  = blockIdx.y;          // 0..63
    const int b   = blockIdx.z;

    size_t ba = ((size_t)b * N_ + n) * 3;
    int   i0 = g_idx[ba+0], i1 = g_idx[ba+1], i2 = g_idx[ba+2];
    int   j0 = g_idx[ba+3], j1 = g_idx[ba+4], j2 = g_idx[ba+5];
    float u0 = g_wt[ba+0],  u1 = g_wt[ba+1],  u2 = g_wt[ba+2];
    float v0 = g_wt[ba+3],  v1 = g_wt[ba+4],  v2 = g_wt[ba+5];

    #pragma unroll
    for (int j = 0; j < 4; ++j) {
        int c = c0 + j * 64;
        const float* f = feat2 + ((size_t)b * C_ + c) * M_;
        float va = u0 * f[i0] + u1 * f[i1] + u2 * f[i2];
        float vb = v0 * f[j0] + v1 * f[j1] + v2 * f[j2];
        size_t oi = ((size_t)b * C_ + c) * N_ + n;
        *(__half2*)(g_interp_h + oi) = __floats2half2_rn(va, vb);
    }
}

// ---------------------------------------------------------------------------
// Kernel 3: fp32 -> fp16 convert (feat1, weights)
// ---------------------------------------------------------------------------
__global__ void conv_kernel(const float* __restrict__ src,
                            __half* __restrict__ dst, int n4)
{
    int i = blockIdx.x * blockDim.x + threadIdx.x;
    if (i >= n4) return;
    float4 v = ((const float4*)src)[i];
    __half2 a = __floats2half2_rn(v.x, v.y);
    __half2 c = __floats2half2_rn(v.z, v.w);
    ((uint2*)dst)[i] = make_uint2(*(uint32_t*)&a, *(uint32_t*)&c);
}

// ---------------------------------------------------------------------------
// Kernel 4: single-pass fp16 GEMM via mma.sync + BN + ReLU.
//   Y[b] = relu( (W @ X[b]) * gamma/sqrt(1+eps) + beta )
//   A = W [O,K] row-major fp16.  B = X [K,N] native fp16 (ldmatrix.trans).
//   fp32 accumulate.  CTA 128x128, BK=32, 8 warps (2x4), warp tile 64x32,
//   3-stage cp.async pipeline, 2 CTAs/SM.
// ---------------------------------------------------------------------------
#define A_ROW   80u            // 32 fp16 = 64B data + 16B pad
#define B_ROW   272u           // 128 fp16 = 256B data + 16B pad
#define OFF_B   10240u         // 128*80
#define STAGE   18944u         // 10240 + 32*272

__global__ __launch_bounds__(256, 2)
void f16_gemm(const __half* __restrict__ W,
              const __half* __restrict__ X0, const __half* __restrict__ X1,
              const float* __restrict__ gamma, const float* __restrict__ beta,
              float* __restrict__ Yf, __half* __restrict__ Yh,
              int K, int Ksplit)
{
    extern __shared__ char smem_raw[];
    const uint32_t sm = smem_u32(smem_raw);
    const int tid  = threadIdx.x;
    const int lane = tid & 31, wid = tid >> 5;
    const int wm = wid >> 2, wn = wid & 3;
    const int bn = blockIdx.x * 128, bo = blockIdx.y * 128, b = blockIdx.z;

    const size_t xs = (size_t)C_ * N_;
    const __half* x0 = X0 + (size_t)b * xs;
    const __half* x1 = X1 + (size_t)b * xs;

    auto prefetch = [&](int s) {
        const uint32_t buf = sm + (uint32_t)(s % 3) * STAGE;
        const int kt = s * 32;
        #pragma unroll
        for (int i = 0; i < 2; i++) {           // A: 128 rows x 4 chunks
            int idx = i * 256 + tid;
            int row = idx >> 2, ch = idx & 3;
            cp16(buf + row * A_ROW + ch * 16,
                 W + (size_t)(bo + row) * K + kt + ch * 8);
        }
        #pragma unroll
        for (int i = 0; i < 2; i++) {           // B: 32 k-rows x 16 chunks
            int idx = i * 256 + tid;
            int kr = idx >> 4, ch = idx & 15;
            int kg = kt + kr;
            const __half* src = (kg < Ksplit) ? (x0 + (size_t)kg * N_)
                                              : (x1 + (size_t)(kg - Ksplit) * N_);
            cp16(buf + OFF_B + kr * B_ROW + ch * 16, src + bn + ch * 8);
        }
        asm volatile("cp.async.commit_group;" ::: "memory");
    };

    float acc[4][4][4];
    #pragma unroll
    for (int i = 0; i < 4; i++)
        #pragma unroll
        for (int j = 0; j < 4; j++)
            #pragma unroll
            for (int k = 0; k < 4; k++) acc[i][j][k] = 0.0f;

    const int nst = K / 32;
    prefetch(0);
    prefetch(1);

    for (int s = 0; s < nst; s++) {
        if (s + 2 < nst) {
            prefetch(s + 2);
            asm volatile("cp.async.wait_group 2;" ::: "memory");
        } else if (s + 1 < nst) {
            asm volatile("cp.async.wait_group 1;" ::: "memory");
        } else {
            asm volatile("cp.async.wait_group 0;" ::: "memory");
        }
        __syncthreads();

        const uint32_t buf = sm + (uint32_t)(s % 3) * STAGE;
        #pragma unroll
        for (int ks = 0; ks < 2; ks++) {
            uint32_t Af[4][4], Bf[4][2];
            const uint32_t arow = wm * 64 + (lane & 15);
            const uint32_t ach  = (uint32_t)(ks * 2) + (lane >> 4);
            #pragma unroll
            for (int mf = 0; mf < 4; mf++)
                ldsm4(Af[mf], buf + (arow + mf * 16) * A_ROW + ach * 16);

            const uint32_t bk = (uint32_t)(ks * 16) + ((lane >> 3) & 1) * 8 + (lane & 7);
            #pragma unroll
            for (int g = 0; g < 2; g++) {
                uint32_t ncol = wn * 32 + g * 16 + (lane >> 4) * 8;
                uint32_t r[4];
                ldsm4t(r, buf + OFF_B + bk * B_ROW + ncol * 2);
                Bf[g*2][0] = r[0]; Bf[g*2][1] = r[1];
                Bf[g*2+1][0] = r[2]; Bf[g*2+1][1] = r[3];
            }
            #pragma unroll
            for (int mf = 0; mf < 4; mf++)
                #pragma unroll
                for (int nf = 0; nf < 4; nf++)
                    mma_f16(acc[mf][nf], Af[mf], Bf[nf]);
        }
        __syncthreads();
    }

    // Epilogue.  Frag (mf,nf): rows = wm*64+mf*16+grp (+8),
    // cols = wn*32+nf*8+qid*2 (+1).
    const int grp = lane >> 2, qid = lane & 3;
    const float bninv = 0.9999950000374997f;  // 1/sqrt(1+1e-5)
    #pragma unroll
    for (int mf = 0; mf < 4; mf++) {
        #pragma unroll
        for (int h = 0; h < 2; h++) {
            int o = bo + wm * 64 + mf * 16 + grp + h * 8;
            float g  = gamma[o] * bninv;
            float bt = beta[o];
            size_t yrow = ((size_t)b * C_ + o) * N_ + bn + wn * 32 + qid * 2;
            #pragma unroll
            for (int nf = 0; nf < 4; nf++) {
                float v0 = fmaxf(fmaf(acc[mf][nf][h*2+0], g, bt), 0.0f);
                float v1 = fmaxf(fmaf(acc[mf][nf][h*2+1], g, bt), 0.0f);
                size_t yo = yrow + nf * 8;
                if (Yh) {
                    *(__half2*)(Yh + yo) = __floats2half2_rn(v0, v1);
                } else {
                    *(float2*)(Yf + yo) = make_float2(v0, v1);
                }
            }
        }
    }
}

// ---------------------------------------------------------------------------
extern "C" void kernel_launch(void* const* d_in, const int* in_sizes, int n_in,
                              void* d_out, int out_size)
{
    const float* xyz1   = (const float*)d_in[0];
    const float* xyz2   = (const float*)d_in[1];
    const float* feat1  = (const float*)d_in[2];
    const float* feat2  = (const float*)d_in[3];
    const float* w1     = (const float*)d_in[4];
    const float* gamma1 = (const float*)d_in[5];
    const float* beta1  = (const float*)d_in[6];
    const float* w2     = (const float*)d_in[7];
    const float* gamma2 = (const float*)d_in[8];
    const float* beta2  = (const float*)d_in[9];
    float* out = (float*)d_out;

    __half *ih, *f1h, *h1h, *w1h, *w2h;
    cudaGetSymbolAddress((void**)&ih,  g_interp_h);
    cudaGetSymbolAddress((void**)&f1h, g_feat1_h);
    cudaGetSymbolAddress((void**)&h1h, g_h1_h);
    cudaGetSymbolAddress((void**)&w1h, g_w1_h);
    cudaGetSymbolAddress((void**)&w2h, g_w2_h);

    const int SMEM_BYTES = 3 * STAGE;   // 56832
    cudaFuncSetAttribute(f16_gemm, cudaFuncAttributeMaxDynamicSharedMemorySize,
                         SMEM_BYTES);

    conv_kernel<<<(C_ * KIN / 4 + 255) / 256, 256>>>(w1, w1h, C_ * KIN / 4);
    conv_kernel<<<(C_ * C_ / 4 + 255) / 256, 256>>>(w2, w2h, C_ * C_ / 4);
    conv_kernel<<<(B_ * C_ * N_ / 4 + 255) / 256, 256>>>(feat1, f1h,
                                                         B_ * C_ * N_ / 4);

    dim3 gknn(N_ / 64, B_);
    knn_kernel<<<gknn, 256>>>(xyz1, xyz2);

    dim3 gint(N_ / 512, 64, B_);
    interp_kernel<<<gint, 256>>>(feat2);

    dim3 gg(N_ / 128, C_ / 128, B_);
    // GEMM1: K=512; B rows <256 from interp, >=256 from feat1; fp16 output
    f16_gemm<<<gg, 256, SMEM_BYTES>>>(w1h, ih, f1h, gamma1, beta1,
                                      (float*)0, h1h, KIN, C_);
    // GEMM2: K=256; fp32 output to d_out
    f16_gemm<<<gg, 256, SMEM_BYTES>>>(w2h, h1h, h1h, gamma2, beta2,
                                      out, (__half*)0, C_, C_);
}

// round 9
// speedup vs baseline: 3.5825x; 1.3395x over previous
#include <cuda_runtime.h>
#include <cuda_fp16.h>
#include <cstdint>
#include <cstddef>

#define B_  16
#define N_  4096
#define M_  1024
#define C_  256
#define KIN 512

// ---------------------------------------------------------------------------
// Scratch (static device globals; allocation is forbidden in kernel_launch)
// ---------------------------------------------------------------------------
__device__ __align__(16) __half g_interp_h[(size_t)B_ * C_ * N_];
__device__ __align__(16) __half g_feat1_h[(size_t)B_ * C_ * N_];
__device__ __align__(16) __half g_h1_h[(size_t)B_ * C_ * N_];
__device__ __align__(16) __half g_w1_h[C_ * KIN];
__device__ __align__(16) __half g_w2_h[C_ * C_];
__device__ float g_pd[(size_t)B_ * N_ * 12];   // partial top-3 dists, 4 parts
__device__ int   g_pi[(size_t)B_ * N_ * 12];   // partial top-3 indices
__device__ int   g_idx[B_ * N_ * 3];
__device__ float g_wt[B_ * N_ * 3];

// ---------------------------------------------------------------------------
// PTX helpers (architecture-portable: sm_80+ instructions only)
// ---------------------------------------------------------------------------
static __device__ __forceinline__ uint32_t smem_u32(const void* p) {
    uint32_t a;
    asm("{ .reg .u64 t; cvta.to.shared.u64 t, %1; cvt.u32.u64 %0, t; }"
        : "=r"(a) : "l"(p));
    return a;
}
static __device__ __forceinline__ void cp16(uint32_t s, const void* g) {
    asm volatile("cp.async.cg.shared.global [%0], [%1], 16;" :: "r"(s), "l"(g));
}
static __device__ __forceinline__ void ldsm4(uint32_t* r, uint32_t a) {
    asm volatile("ldmatrix.sync.aligned.m8n8.x4.shared.b16 {%0,%1,%2,%3}, [%4];"
                 : "=r"(r[0]), "=r"(r[1]), "=r"(r[2]), "=r"(r[3]) : "r"(a));
}
static __device__ __forceinline__ void ldsm4t(uint32_t* r, uint32_t a) {
    asm volatile("ldmatrix.sync.aligned.m8n8.x4.trans.shared.b16 {%0,%1,%2,%3}, [%4];"
                 : "=r"(r[0]), "=r"(r[1]), "=r"(r[2]), "=r"(r[3]) : "r"(a));
}
static __device__ __forceinline__ void mma_f16(float* c, const uint32_t* a,
                                               const uint32_t* b) {
    asm volatile(
        "mma.sync.aligned.m16n8k16.row.col.f32.f16.f16.f32 "
        "{%0,%1,%2,%3}, {%4,%5,%6,%7}, {%8,%9}, {%0,%1,%2,%3};"
        : "+f"(c[0]), "+f"(c[1]), "+f"(c[2]), "+f"(c[3])
        : "r"(a[0]), "r"(a[1]), "r"(a[2]), "r"(a[3]), "r"(b[0]), "r"(b[1]));
}

// ---------------------------------------------------------------------------
// Kernel 0: fused fp32 -> fp16 convert (w1 | w2 | feat1) in one launch
// ---------------------------------------------------------------------------
#define N4_W1 32768
#define N4_W2 16384
#define N4_F1 4194304
__global__ void conv_fused(const float* __restrict__ w1,
                           const float* __restrict__ w2,
                           const float* __restrict__ f1,
                           __half* __restrict__ w1h,
                           __half* __restrict__ w2h,
                           __half* __restrict__ f1h)
{
    int i = blockIdx.x * 256 + threadIdx.x;
    const float* src; __half* dst; int off;
    if (i < N4_W1)                 { src = w1; dst = w1h; off = i; }
    else if (i < N4_W1 + N4_W2)    { src = w2; dst = w2h; off = i - N4_W1; }
    else if (i < N4_W1 + N4_W2 + N4_F1) {
        src = f1; dst = f1h; off = i - N4_W1 - N4_W2;
    } else return;
    float4 v = ((const float4*)src)[off];
    __half2 a = __floats2half2_rn(v.x, v.y);
    __half2 c = __floats2half2_rn(v.z, v.w);
    ((uint2*)dst)[off] = make_uint2(*(uint32_t*)&a, *(uint32_t*)&c);
}

// ---------------------------------------------------------------------------
// Kernel 1: 3-NN pass 1 — candidates split across CTAs (NOT lanes).
// grid (N_/256, 4, B_): each CTA scans one 256-candidate tile for 256
// queries using the full-warp-broadcast LDS loop (the pattern that ran at
// 55us/4 ~ 14us).  Writes per-part top-3 (d, idx) partials.
// ---------------------------------------------------------------------------
__global__ void knn_part(const float* __restrict__ xyz1,
                         const float* __restrict__ xyz2)
{
    __shared__ float4 sp[256];
    const int tid  = threadIdx.x;
    const int part = blockIdx.y;
    const int b    = blockIdx.z;
    const int n    = blockIdx.x * 256 + tid;
    const int mbase = part * 256;

    {
        const float* p2 = xyz2 + ((size_t)b * M_ + mbase + tid) * 3;
        float x = p2[0], y = p2[1], z = p2[2];
        sp[tid] = make_float4(x, y, z, x * x + y * y + z * z);
    }
    const float* p1 = xyz1 + ((size_t)b * N_ + n) * 3;
    const float px = p1[0], py = p1[1], pz = p1[2];
    const float s1 = px * px + py * py + pz * pz;
    __syncthreads();

    float b0 = 3.4e38f, b1 = 3.4e38f, b2 = 3.4e38f;
    int   i0 = 0, i1 = 0, i2 = 0;
    #pragma unroll 8
    for (int j = 0; j < 256; ++j) {
        float4 q = sp[j];
        float dot = px * q.x + py * q.y + pz * q.z;
        float d2  = (s1 + q.w) - 2.0f * dot;
        int   m   = mbase + j;
        if (d2 < b2) {
            if (d2 < b1) {
                if (d2 < b0) { b2 = b1; i2 = i1; b1 = b0; i1 = i0; b0 = d2; i0 = m; }
                else         { b2 = b1; i2 = i1; b1 = d2; i1 = m; }
            } else           { b2 = d2; i2 = m; }
        }
    }

    size_t o = ((size_t)b * N_ + n) * 12 + part * 3;
    g_pd[o+0] = b0; g_pd[o+1] = b1; g_pd[o+2] = b2;
    g_pi[o+0] = i0; g_pi[o+1] = i1; g_pi[o+2] = i2;
}

// ---------------------------------------------------------------------------
// Kernel 2: merge the 4 per-part top-3 lists -> final idx/weights.
// Lexicographic (d, idx) insert preserves top_k's lowest-index tie-break
// (parts hold disjoint ascending index ranges and are processed in order).
// ---------------------------------------------------------------------------
__global__ void knn_merge()
{
    int q = blockIdx.x * 256 + threadIdx.x;     // 0 .. B_*N_-1
    size_t o = (size_t)q * 12;

    float b0 = g_pd[o+0], b1 = g_pd[o+1], b2 = g_pd[o+2];
    int   i0 = g_pi[o+0], i1 = g_pi[o+1], i2 = g_pi[o+2];

    #pragma unroll
    for (int part = 1; part < 4; ++part) {
        #pragma unroll
        for (int e = 0; e < 3; ++e) {
            float d = g_pd[o + part*3 + e];
            int   m = g_pi[o + part*3 + e];
            bool l2 = (d < b2) || (d == b2 && m < i2);
            if (l2) {
                bool l1 = (d < b1) || (d == b1 && m < i1);
                if (l1) {
                    bool l0 = (d < b0) || (d == b0 && m < i0);
                    if (l0) { b2 = b1; i2 = i1; b1 = b0; i1 = i0; b0 = d; i0 = m; }
                    else    { b2 = b1; i2 = i1; b1 = d; i1 = m; }
                } else      { b2 = d; i2 = m; }
            }
        }
    }

    float w0 = 1.0f / (b0 + 1e-8f);
    float w1 = 1.0f / (b1 + 1e-8f);
    float w2 = 1.0f / (b2 + 1e-8f);
    float ws = w0 + w1 + w2;
    g_idx[q*3+0] = i0; g_idx[q*3+1] = i1; g_idx[q*3+2] = i2;
    g_wt[q*3+0] = w0 / ws; g_wt[q*3+1] = w1 / ws; g_wt[q*3+2] = w2 / ws;
}

// ---------------------------------------------------------------------------
// Kernel 3: weighted 3-point gather -> interp as fp16 (unchanged)
// ---------------------------------------------------------------------------
__global__ void interp_kernel(const float* __restrict__ feat2)
{
    const int tid = threadIdx.x;
    const int n   = (blockIdx.x * 256 + tid) * 2;
    const int c0  = blockIdx.y;          // 0..63
    const int b   = blockIdx.z;

    size_t ba = ((size_t)b * N_ + n) * 3;
    int   i0 = g_idx[ba+0], i1 = g_idx[ba+1], i2 = g_idx[ba+2];
    int   j0 = g_idx[ba+3], j1 = g_idx[ba+4], j2 = g_idx[ba+5];
    float u0 = g_wt[ba+0],  u1 = g_wt[ba+1],  u2 = g_wt[ba+2];
    float v0 = g_wt[ba+3],  v1 = g_wt[ba+4],  v2 = g_wt[ba+5];

    #pragma unroll
    for (int j = 0; j < 4; ++j) {
        int c = c0 + j * 64;
        const float* f = feat2 + ((size_t)b * C_ + c) * M_;
        float va = u0 * f[i0] + u1 * f[i1] + u2 * f[i2];
        float vb = v0 * f[j0] + v1 * f[j1] + v2 * f[j2];
        size_t oi = ((size_t)b * C_ + c) * N_ + n;
        *(__half2*)(g_interp_h + oi) = __floats2half2_rn(va, vb);
    }
}

// ---------------------------------------------------------------------------
// Kernel 4: single-pass fp16 GEMM via mma.sync + BN + ReLU (unchanged).
// ---------------------------------------------------------------------------
#define A_ROW   80u            // 32 fp16 = 64B data + 16B pad
#define B_ROW   272u           // 128 fp16 = 256B data + 16B pad
#define OFF_B   10240u         // 128*80
#define STAGE   18944u         // 10240 + 32*272

__global__ __launch_bounds__(256, 2)
void f16_gemm(const __half* __restrict__ W,
              const __half* __restrict__ X0, const __half* __restrict__ X1,
              const float* __restrict__ gamma, const float* __restrict__ beta,
              float* __restrict__ Yf, __half* __restrict__ Yh,
              int K, int Ksplit)
{
    extern __shared__ char smem_raw[];
    const uint32_t sm = smem_u32(smem_raw);
    const int tid  = threadIdx.x;
    const int lane = tid & 31, wid = tid >> 5;
    const int wm = wid >> 2, wn = wid & 3;
    const int bn = blockIdx.x * 128, bo = blockIdx.y * 128, b = blockIdx.z;

    const size_t xs = (size_t)C_ * N_;
    const __half* x0 = X0 + (size_t)b * xs;
    const __half* x1 = X1 + (size_t)b * xs;

    auto prefetch = [&](int s) {
        const uint32_t buf = sm + (uint32_t)(s % 3) * STAGE;
        const int kt = s * 32;
        #pragma unroll
        for (int i = 0; i < 2; i++) {           // A: 128 rows x 4 chunks
            int idx = i * 256 + tid;
            int row = idx >> 2, ch = idx & 3;
            cp16(buf + row * A_ROW + ch * 16,
                 W + (size_t)(bo + row) * K + kt + ch * 8);
        }
        #pragma unroll
        for (int i = 0; i < 2; i++) {           // B: 32 k-rows x 16 chunks
            int idx = i * 256 + tid;
            int kr = idx >> 4, ch = idx & 15;
            int kg = kt + kr;
            const __half* src = (kg < Ksplit) ? (x0 + (size_t)kg * N_)
                                              : (x1 + (size_t)(kg - Ksplit) * N_);
            cp16(buf + OFF_B + kr * B_ROW + ch * 16, src + bn + ch * 8);
        }
        asm volatile("cp.async.commit_group;" ::: "memory");
    };

    float acc[4][4][4];
    #pragma unroll
    for (int i = 0; i < 4; i++)
        #pragma unroll
        for (int j = 0; j < 4; j++)
            #pragma unroll
            for (int k = 0; k < 4; k++) acc[i][j][k] = 0.0f;

    const int nst = K / 32;
    prefetch(0);
    prefetch(1);

    for (int s = 0; s < nst; s++) {
        if (s + 2 < nst) {
            prefetch(s + 2);
            asm volatile("cp.async.wait_group 2;" ::: "memory");
        } else if (s + 1 < nst) {
            asm volatile("cp.async.wait_group 1;" ::: "memory");
        } else {
            asm volatile("cp.async.wait_group 0;" ::: "memory");
        }
        __syncthreads();

        const uint32_t buf = sm + (uint32_t)(s % 3) * STAGE;
        #pragma unroll
        for (int ks = 0; ks < 2; ks++) {
            uint32_t Af[4][4], Bf[4][2];
            const uint32_t arow = wm * 64 + (lane & 15);
            const uint32_t ach  = (uint32_t)(ks * 2) + (lane >> 4);
            #pragma unroll
            for (int mf = 0; mf < 4; mf++)
                ldsm4(Af[mf], buf + (arow + mf * 16) * A_ROW + ach * 16);

            const uint32_t bk = (uint32_t)(ks * 16) + ((lane >> 3) & 1) * 8 + (lane & 7);
            #pragma unroll
            for (int g = 0; g < 2; g++) {
                uint32_t ncol = wn * 32 + g * 16 + (lane >> 4) * 8;
                uint32_t r[4];
                ldsm4t(r, buf + OFF_B + bk * B_ROW + ncol * 2);
                Bf[g*2][0] = r[0]; Bf[g*2][1] = r[1];
                Bf[g*2+1][0] = r[2]; Bf[g*2+1][1] = r[3];
            }
            #pragma unroll
            for (int mf = 0; mf < 4; mf++)
                #pragma unroll
                for (int nf = 0; nf < 4; nf++)
                    mma_f16(acc[mf][nf], Af[mf], Bf[nf]);
        }
        __syncthreads();
    }

    // Epilogue.  Frag (mf,nf): rows = wm*64+mf*16+grp (+8),
    // cols = wn*32+nf*8+qid*2 (+1).
    const int grp = lane >> 2, qid = lane & 3;
    const float bninv = 0.9999950000374997f;  // 1/sqrt(1+1e-5)
    #pragma unroll
    for (int mf = 0; mf < 4; mf++) {
        #pragma unroll
        for (int h = 0; h < 2; h++) {
            int o = bo + wm * 64 + mf * 16 + grp + h * 8;
            float g  = gamma[o] * bninv;
            float bt = beta[o];
            size_t yrow = ((size_t)b * C_ + o) * N_ + bn + wn * 32 + qid * 2;
            #pragma unroll
            for (int nf = 0; nf < 4; nf++) {
                float v0 = fmaxf(fmaf(acc[mf][nf][h*2+0], g, bt), 0.0f);
                float v1 = fmaxf(fmaf(acc[mf][nf][h*2+1], g, bt), 0.0f);
                size_t yo = yrow + nf * 8;
                if (Yh) {
                    *(__half2*)(Yh + yo) = __floats2half2_rn(v0, v1);
                } else {
                    *(float2*)(Yf + yo) = make_float2(v0, v1);
                }
            }
        }
    }
}

// ---------------------------------------------------------------------------
extern "C" void kernel_launch(void* const* d_in, const int* in_sizes, int n_in,
                              void* d_out, int out_size)
{
    const float* xyz1   = (const float*)d_in[0];
    const float* xyz2   = (const float*)d_in[1];
    const float* feat1  = (const float*)d_in[2];
    const float* feat2  = (const float*)d_in[3];
    const float* w1     = (const float*)d_in[4];
    const float* gamma1 = (const float*)d_in[5];
    const float* beta1  = (const float*)d_in[6];
    const float* w2     = (const float*)d_in[7];
    const float* gamma2 = (const float*)d_in[8];
    const float* beta2  = (const float*)d_in[9];
    float* out = (float*)d_out;

    __half *ih, *f1h, *h1h, *w1h, *w2h;
    cudaGetSymbolAddress((void**)&ih,  g_interp_h);
    cudaGetSymbolAddress((void**)&f1h, g_feat1_h);
    cudaGetSymbolAddress((void**)&h1h, g_h1_h);
    cudaGetSymbolAddress((void**)&w1h, g_w1_h);
    cudaGetSymbolAddress((void**)&w2h, g_w2_h);

    const int SMEM_BYTES = 3 * STAGE;   // 56832
    cudaFuncSetAttribute(f16_gemm, cudaFuncAttributeMaxDynamicSharedMemorySize,
                         SMEM_BYTES);

    // Launch order (profiled launch = index 3 = interp_kernel):
    // 0:conv_fused  1:knn_part  2:knn_merge  3:interp  4:gemm1  5:gemm2
    const int n4tot = N4_W1 + N4_W2 + N4_F1;
    conv_fused<<<(n4tot + 255) / 256, 256>>>(w1, w2, feat1, w1h, w2h, f1h);

    dim3 gknn(N_ / 256, 4, B_);
    knn_part<<<gknn, 256>>>(xyz1, xyz2);
    knn_merge<<<B_ * N_ / 256, 256>>>();

    dim3 gint(N_ / 512, 64, B_);
    interp_kernel<<<gint, 256>>>(feat2);

    dim3 gg(N_ / 128, C_ / 128, B_);
    // GEMM1: K=512; B rows <256 from interp, >=256 from feat1; fp16 output
    f16_gemm<<<gg, 256, SMEM_BYTES>>>(w1h, ih, f1h, gamma1, beta1,
                                      (float*)0, h1h, KIN, C_);
    // GEMM2: K=256; fp32 output to d_out
    f16_gemm<<<gg, 256, SMEM_BYTES>>>(w2h, h1h, h1h, gamma2, beta2,
                                      out, (__half*)0, C_, C_);
}

// round 10
// speedup vs baseline: 3.7848x; 1.0565x over previous
#include <cuda_runtime.h>
#include <cuda_fp16.h>
#include <cstdint>
#include <cstddef>

#define B_  16
#define N_  4096
#define M_  1024
#define C_  256
#define KIN 512

// ---------------------------------------------------------------------------
// Scratch (static device globals; allocation is forbidden in kernel_launch)
// ---------------------------------------------------------------------------
__device__ __align__(16) __half g_f2t[(size_t)B_ * M_ * C_];    // feat2^T [B][M][C]
__device__ __align__(16) __half g_x1[(size_t)B_ * N_ * KIN];    // GEMM1 B, n-major
__device__ __align__(16) __half g_h1[(size_t)B_ * C_ * N_];     // h1, k-major
__device__ __align__(16) __half g_w1h[C_ * KIN];
__device__ __align__(16) __half g_w2h[C_ * C_];
__device__ float g_pd[(size_t)B_ * N_ * 12];   // partial top-3 dists, 4 parts
__device__ int   g_pi[(size_t)B_ * N_ * 12];   // partial top-3 indices

// ---------------------------------------------------------------------------
// PTX helpers (architecture-portable: sm_80+ instructions only)
// ---------------------------------------------------------------------------
static __device__ __forceinline__ uint32_t smem_u32(const void* p) {
    uint32_t a;
    asm("{ .reg .u64 t; cvta.to.shared.u64 t, %1; cvt.u32.u64 %0, t; }"
        : "=r"(a) : "l"(p));
    return a;
}
static __device__ __forceinline__ void cp16(uint32_t s, const void* g) {
    asm volatile("cp.async.cg.shared.global [%0], [%1], 16;" :: "r"(s), "l"(g));
}
static __device__ __forceinline__ void ldsm4(uint32_t* r, uint32_t a) {
    asm volatile("ldmatrix.sync.aligned.m8n8.x4.shared.b16 {%0,%1,%2,%3}, [%4];"
                 : "=r"(r[0]), "=r"(r[1]), "=r"(r[2]), "=r"(r[3]) : "r"(a));
}
static __device__ __forceinline__ void ldsm4t(uint32_t* r, uint32_t a) {
    asm volatile("ldmatrix.sync.aligned.m8n8.x4.trans.shared.b16 {%0,%1,%2,%3}, [%4];"
                 : "=r"(r[0]), "=r"(r[1]), "=r"(r[2]), "=r"(r[3]) : "r"(a));
}
static __device__ __forceinline__ void mma_f16(float* c, const uint32_t* a,
                                               const uint32_t* b) {
    asm volatile(
        "mma.sync.aligned.m16n8k16.row.col.f32.f16.f16.f32 "
        "{%0,%1,%2,%3}, {%4,%5,%6,%7}, {%8,%9}, {%0,%1,%2,%3};"
        : "+f"(c[0]), "+f"(c[1]), "+f"(c[2]), "+f"(c[3])
        : "r"(a[0]), "r"(a[1]), "r"(a[2]), "r"(a[3]), "r"(b[0]), "r"(b[1]));
}

// ---------------------------------------------------------------------------
// Kernel 0: fused preprocessing, partitioned by blockIdx.x:
//   [0, 4096)        feat2 [B][C][M] fp32 -> g_f2t [B][M][C] fp16 (32x32 tiles)
//   [4096, 20480)    feat1 [B][C][N] fp32 -> g_x1[n][256..511] fp16 (transpose)
//   [20480, 20608)   w1 fp32 -> fp16
//   [20608, 20672)   w2 fp32 -> fp16
// ---------------------------------------------------------------------------
#define G_F2T 4096
#define G_F1T 20480
#define G_W1  20608
#define G_W2  20672
__global__ void pre_kernel(const float* __restrict__ feat2,
                           const float* __restrict__ feat1,
                           const float* __restrict__ w1,
                           const float* __restrict__ w2)
{
    __shared__ float tile[32][33];
    const int blk = blockIdx.x, tid = threadIdx.x;

    if (blk < G_F2T) {                       // feat2 transpose: 16b x 8c x 32m
        int b = blk >> 8, rem = blk & 255;
        int c0 = (rem >> 5) * 32, m0 = (rem & 31) * 32;
        int ml = tid & 31, cl = tid >> 5;
        #pragma unroll
        for (int i = 0; i < 4; i++) {
            int c = cl + i * 8;
            tile[c][ml] = feat2[((size_t)(b * C_ + c0 + c)) * M_ + m0 + ml];
        }
        __syncthreads();
        int cp = tid & 15, mr = tid >> 4;
        #pragma unroll
        for (int i = 0; i < 2; i++) {
            int m = mr + i * 16;
            __half2 h = __floats2half2_rn(tile[cp*2][m], tile[cp*2+1][m]);
            *(__half2*)(g_f2t + ((size_t)(b * M_ + m0 + m)) * C_ + c0 + cp*2) = h;
        }
    } else if (blk < G_F1T) {                // feat1 transpose: 16b x 8c x 128n
        int q = blk - G_F2T;
        int b = q >> 10, rem = q & 1023;
        int c0 = (rem >> 7) * 32, n0 = (rem & 127) * 32;
        int nl = tid & 31, cl = tid >> 5;
        #pragma unroll
        for (int i = 0; i < 4; i++) {
            int c = cl + i * 8;
            tile[c][nl] = feat1[((size_t)(b * C_ + c0 + c)) * N_ + n0 + nl];
        }
        __syncthreads();
        int cp = tid & 15, nr = tid >> 4;
        #pragma unroll
        for (int i = 0; i < 2; i++) {
            int n = nr + i * 16;
            __half2 h = __floats2half2_rn(tile[cp*2][n], tile[cp*2+1][n]);
            *(__half2*)(g_x1 + ((size_t)(b * N_ + n0 + n)) * KIN
                              + C_ + c0 + cp*2) = h;
        }
    } else if (blk < G_W1) {                 // w1 convert (float4 units)
        int i = (blk - G_F1T) * 256 + tid;
        float4 v = ((const float4*)w1)[i];
        __half2 a = __floats2half2_rn(v.x, v.y);
        __half2 c = __floats2half2_rn(v.z, v.w);
        ((uint2*)g_w1h)[i] = make_uint2(*(uint32_t*)&a, *(uint32_t*)&c);
    } else {                                 // w2 convert
        int i = (blk - G_W1) * 256 + tid;
        float4 v = ((const float4*)w2)[i];
        __half2 a = __floats2half2_rn(v.x, v.y);
        __half2 c = __floats2half2_rn(v.z, v.w);
        ((uint2*)g_w2h)[i] = make_uint2(*(uint32_t*)&a, *(uint32_t*)&c);
    }
}

// ---------------------------------------------------------------------------
// Kernel 1: 3-NN pass 1 — candidates split across CTAs (proven in R9).
// ---------------------------------------------------------------------------
__global__ void knn_part(const float* __restrict__ xyz1,
                         const float* __restrict__ xyz2)
{
    __shared__ float4 sp[256];
    const int tid  = threadIdx.x;
    const int part = blockIdx.y;
    const int b    = blockIdx.z;
    const int n    = blockIdx.x * 256 + tid;
    const int mbase = part * 256;

    {
        const float* p2 = xyz2 + ((size_t)b * M_ + mbase + tid) * 3;
        float x = p2[0], y = p2[1], z = p2[2];
        sp[tid] = make_float4(x, y, z, x * x + y * y + z * z);
    }
    const float* p1 = xyz1 + ((size_t)b * N_ + n) * 3;
    const float px = p1[0], py = p1[1], pz = p1[2];
    const float s1 = px * px + py * py + pz * pz;
    __syncthreads();

    float b0 = 3.4e38f, b1 = 3.4e38f, b2 = 3.4e38f;
    int   i0 = 0, i1 = 0, i2 = 0;
    #pragma unroll 8
    for (int j = 0; j < 256; ++j) {
        float4 q = sp[j];
        float dot = px * q.x + py * q.y + pz * q.z;
        float d2  = (s1 + q.w) - 2.0f * dot;
        int   m   = mbase + j;
        if (d2 < b2) {
            if (d2 < b1) {
                if (d2 < b0) { b2 = b1; i2 = i1; b1 = b0; i1 = i0; b0 = d2; i0 = m; }
                else         { b2 = b1; i2 = i1; b1 = d2; i1 = m; }
            } else           { b2 = d2; i2 = m; }
        }
    }

    size_t o = ((size_t)b * N_ + n) * 12 + part * 3;
    g_pd[o+0] = b0; g_pd[o+1] = b1; g_pd[o+2] = b2;
    g_pi[o+0] = i0; g_pi[o+1] = i1; g_pi[o+2] = i2;
}

// ---------------------------------------------------------------------------
// Kernel 2: fused merge + interpolate, one warp per query point.
// All lanes redundantly merge the 4 partial top-3 lists (broadcast loads),
// then gather 3 contiguous 512B rows from g_f2t (coalesced) and write the
// weighted sum n-major into g_x1[n][0..255] (coalesced 512B store).
// ---------------------------------------------------------------------------
__global__ void interp_merge()
{
    const int tid = threadIdx.x, wid = tid >> 5, lane = tid & 31;
    const int b = blockIdx.y;
    const int n = blockIdx.x * 8 + wid;

    size_t o = ((size_t)b * N_ + n) * 12;
    float b0 = g_pd[o+0], b1 = g_pd[o+1], b2 = g_pd[o+2];
    int   i0 = g_pi[o+0], i1 = g_pi[o+1], i2 = g_pi[o+2];
    #pragma unroll
    for (int part = 1; part < 4; ++part) {
        #pragma unroll
        for (int e = 0; e < 3; ++e) {
            float d = g_pd[o + part*3 + e];
            int   m = g_pi[o + part*3 + e];
            bool l2 = (d < b2) || (d == b2 && m < i2);
            if (l2) {
                bool l1 = (d < b1) || (d == b1 && m < i1);
                if (l1) {
                    bool l0 = (d < b0) || (d == b0 && m < i0);
                    if (l0) { b2 = b1; i2 = i1; b1 = b0; i1 = i0; b0 = d; i0 = m; }
                    else    { b2 = b1; i2 = i1; b1 = d; i1 = m; }
                } else      { b2 = d; i2 = m; }
            }
        }
    }
    float w0 = 1.0f / (b0 + 1e-8f);
    float w1 = 1.0f / (b1 + 1e-8f);
    float w2 = 1.0f / (b2 + 1e-8f);
    float ws = w0 + w1 + w2;
    w0 /= ws; w1 /= ws; w2 /= ws;

    const __half* r0 = g_f2t + ((size_t)b * M_ + i0) * C_ + lane * 8;
    const __half* r1 = g_f2t + ((size_t)b * M_ + i1) * C_ + lane * 8;
    const __half* r2 = g_f2t + ((size_t)b * M_ + i2) * C_ + lane * 8;
    uint4 u0 = *(const uint4*)r0;
    uint4 u1 = *(const uint4*)r1;
    uint4 u2 = *(const uint4*)r2;
    const __half2* h0 = (const __half2*)&u0;
    const __half2* h1 = (const __half2*)&u1;
    const __half2* h2 = (const __half2*)&u2;

    uint4 outp;
    __half2* op = (__half2*)&outp;
    #pragma unroll
    for (int j = 0; j < 4; j++) {
        float2 a = __half22float2(h0[j]);
        float2 c = __half22float2(h1[j]);
        float2 d = __half22float2(h2[j]);
        op[j] = __floats2half2_rn(w0 * a.x + w1 * c.x + w2 * d.x,
                                  w0 * a.y + w1 * c.y + w2 * d.y);
    }
    *(uint4*)(g_x1 + ((size_t)b * N_ + n) * KIN + lane * 8) = outp;
}

// ---------------------------------------------------------------------------
// Kernel 3: fp16 GEMM via mma.sync + BN + ReLU, templated on B layout.
//   NM=true : B n-major [N][K] (g_x1), fragments via ldmatrix non-trans.
//   NM=false: B k-major [K][N] (h1),  fragments via ldmatrix trans (proven).
// ---------------------------------------------------------------------------
#define A_ROW   80u            // 32 fp16 = 64B data + 16B pad
#define BK_ROW  272u           // k-major: 128 fp16 = 256B + 16B pad
#define BN_ROW  80u            // n-major: 32 fp16 = 64B + 16B pad
#define OFF_B   10240u         // A region = 128*80

template<bool NM>
__global__ __launch_bounds__(256, 2)
void f16_gemm(const __half* __restrict__ W,
              const __half* __restrict__ X0, const __half* __restrict__ X1,
              const float* __restrict__ gamma, const float* __restrict__ beta,
              float* __restrict__ Yf, __half* __restrict__ Yh,
              int K, int Ksplit)
{
    constexpr uint32_t STAGE = NM ? 20480u : 18944u;
    extern __shared__ char smem_raw[];
    const uint32_t sm = smem_u32(smem_raw);
    const int tid  = threadIdx.x;
    const int lane = tid & 31, wid = tid >> 5;
    const int wm = wid >> 2, wn = wid & 3;
    const int bn = blockIdx.x * 128, bo = blockIdx.y * 128, b = blockIdx.z;

    const __half* x0 = X0 + (size_t)b * ((size_t)(NM ? N_ * KIN : C_ * N_));
    const __half* x1 = NM ? x0 : (X1 + (size_t)b * C_ * N_);

    auto prefetch = [&](int s) {
        const uint32_t buf = sm + (uint32_t)(s % 3) * STAGE;
        const int kt = s * 32;
        #pragma unroll
        for (int i = 0; i < 2; i++) {           // A: 128 rows x 4 chunks
            int idx = i * 256 + tid;
            int row = idx >> 2, ch = idx & 3;
            cp16(buf + row * A_ROW + ch * 16,
                 W + (size_t)(bo + row) * K + kt + ch * 8);
        }
        if (NM) {                               // B n-major: 128 n-rows x 4 chunks
            #pragma unroll
            for (int i = 0; i < 2; i++) {
                int idx = i * 256 + tid;
                int row = idx >> 2, ch = idx & 3;
                cp16(buf + OFF_B + row * BN_ROW + ch * 16,
                     x0 + (size_t)(bn + row) * KIN + kt + ch * 8);
            }
        } else {                                // B k-major: 32 k-rows x 16 chunks
            #pragma unroll
            for (int i = 0; i < 2; i++) {
                int idx = i * 256 + tid;
                int kr = idx >> 4, ch = idx & 15;
                int kg = kt + kr;
                const __half* src = (kg < Ksplit)
                                  ? (x0 + (size_t)kg * N_)
                                  : (x1 + (size_t)(kg - Ksplit) * N_);
                cp16(buf + OFF_B + kr * BK_ROW + ch * 16, src + bn + ch * 8);
            }
        }
        asm volatile("cp.async.commit_group;" ::: "memory");
    };

    float acc[4][4][4];
    #pragma unroll
    for (int i = 0; i < 4; i++)
        #pragma unroll
        for (int j = 0; j < 4; j++)
            #pragma unroll
            for (int k = 0; k < 4; k++) acc[i][j][k] = 0.0f;

    const int nst = K / 32;
    prefetch(0);
    prefetch(1);

    for (int s = 0; s < nst; s++) {
        if (s + 2 < nst) {
            prefetch(s + 2);
            asm volatile("cp.async.wait_group 2;" ::: "memory");
        } else if (s + 1 < nst) {
            asm volatile("cp.async.wait_group 1;" ::: "memory");
        } else {
            asm volatile("cp.async.wait_group 0;" ::: "memory");
        }
        __syncthreads();

        const uint32_t buf = sm + (uint32_t)(s % 3) * STAGE;
        #pragma unroll
        for (int ks = 0; ks < 2; ks++) {
            uint32_t Af[4][4], Bf[4][2];
            const uint32_t arow = wm * 64 + (lane & 15);
            const uint32_t ach  = (uint32_t)(ks * 2) + (lane >> 4);
            #pragma unroll
            for (int mf = 0; mf < 4; mf++)
                ldsm4(Af[mf], buf + (arow + mf * 16) * A_ROW + ach * 16);

            if (NM) {
                // rows = n (A-style map): r0=(n0-7,klo) r1=(n8-15,klo)
                //                         r2=(n0-7,khi) r3=(n8-15,khi)
                #pragma unroll
                for (int g = 0; g < 2; g++) {
                    uint32_t nrow = wn * 32 + g * 16 + (lane & 15);
                    uint32_t r[4];
                    ldsm4(r, buf + OFF_B + nrow * BN_ROW + ach * 16);
                    Bf[g*2][0]   = r[0]; Bf[g*2][1]   = r[2];
                    Bf[g*2+1][0] = r[1]; Bf[g*2+1][1] = r[3];
                }
            } else {
                const uint32_t bk = (uint32_t)(ks * 16)
                                  + ((lane >> 3) & 1) * 8 + (lane & 7);
                #pragma unroll
                for (int g = 0; g < 2; g++) {
                    uint32_t ncol = wn * 32 + g * 16 + (lane >> 4) * 8;
                    uint32_t r[4];
                    ldsm4t(r, buf + OFF_B + bk * BK_ROW + ncol * 2);
                    Bf[g*2][0]   = r[0]; Bf[g*2][1]   = r[1];
                    Bf[g*2+1][0] = r[2]; Bf[g*2+1][1] = r[3];
                }
            }
            #pragma unroll
            for (int mf = 0; mf < 4; mf++)
                #pragma unroll
                for (int nf = 0; nf < 4; nf++)
                    mma_f16(acc[mf][nf], Af[mf], Bf[nf]);
        }
        __syncthreads();
    }

    // Epilogue.  Frag (mf,nf): rows = wm*64+mf*16+grp (+8),
    // cols = wn*32+nf*8+qid*2 (+1).
    const int grp = lane >> 2, qid = lane & 3;
    const float bninv = 0.9999950000374997f;  // 1/sqrt(1+1e-5)
    #pragma unroll
    for (int mf = 0; mf < 4; mf++) {
        #pragma unroll
        for (int h = 0; h < 2; h++) {
            int o = bo + wm * 64 + mf * 16 + grp + h * 8;
            float g  = gamma[o] * bninv;
            float bt = beta[o];
            size_t yrow = ((size_t)b * C_ + o) * N_ + bn + wn * 32 + qid * 2;
            #pragma unroll
            for (int nf = 0; nf < 4; nf++) {
                float v0 = fmaxf(fmaf(acc[mf][nf][h*2+0], g, bt), 0.0f);
                float v1 = fmaxf(fmaf(acc[mf][nf][h*2+1], g, bt), 0.0f);
                size_t yo = yrow + nf * 8;
                if (Yh) {
                    *(__half2*)(Yh + yo) = __floats2half2_rn(v0, v1);
                } else {
                    *(float2*)(Yf + yo) = make_float2(v0, v1);
                }
            }
        }
    }
}

// ---------------------------------------------------------------------------
extern "C" void kernel_launch(void* const* d_in, const int* in_sizes, int n_in,
                              void* d_out, int out_size)
{
    const float* xyz1   = (const float*)d_in[0];
    const float* xyz2   = (const float*)d_in[1];
    const float* feat1  = (const float*)d_in[2];
    const float* feat2  = (const float*)d_in[3];
    const float* w1     = (const float*)d_in[4];
    const float* gamma1 = (const float*)d_in[5];
    const float* beta1  = (const float*)d_in[6];
    const float* w2     = (const float*)d_in[7];
    const float* gamma2 = (const float*)d_in[8];
    const float* beta2  = (const float*)d_in[9];
    float* out = (float*)d_out;

    __half *x1p, *h1p, *w1p, *w2p;
    cudaGetSymbolAddress((void**)&x1p, g_x1);
    cudaGetSymbolAddress((void**)&h1p, g_h1);
    cudaGetSymbolAddress((void**)&w1p, g_w1h);
    cudaGetSymbolAddress((void**)&w2p, g_w2h);

    const int SMEM_NM = 3 * 20480;   // 61440
    const int SMEM_KM = 3 * 18944;   // 56832
    cudaFuncSetAttribute(f16_gemm<true>,
                         cudaFuncAttributeMaxDynamicSharedMemorySize, SMEM_NM);
    cudaFuncSetAttribute(f16_gemm<false>,
                         cudaFuncAttributeMaxDynamicSharedMemorySize, SMEM_KM);

    // Launch order (profiled launch = index 3 = gemm1):
    // 0:pre  1:knn_part  2:interp_merge  3:gemm1  4:gemm2
    pre_kernel<<<G_W2, 256>>>(feat2, feat1, w1, w2);

    dim3 gknn(N_ / 256, 4, B_);
    knn_part<<<gknn, 256>>>(xyz1, xyz2);

    dim3 gim(N_ / 8, B_);
    interp_merge<<<gim, 256>>>();

    dim3 gg(N_ / 128, C_ / 128, B_);
    // GEMM1: K=512, B n-major from g_x1; fp16 k-major output h1
    f16_gemm<true><<<gg, 256, SMEM_NM>>>(w1p, x1p, x1p, gamma1, beta1,
                                         (float*)0, h1p, KIN, C_);
    // GEMM2: K=256, B k-major from h1; fp32 output to d_out
    f16_gemm<false><<<gg, 256, SMEM_KM>>>(w2p, h1p, h1p, gamma2, beta2,
                                          out, (__half*)0, C_, C_);
}